// round 5
// baseline (speedup 1.0000x reference)
#include <cuda_runtime.h>
#include <math.h>

// Reproduce: y = irfft(rfft(x, n=139263) * rfft(h, n=139263))[..., :131072]
// with the rfft grid N1=139263 (odd) and irfft default grid N2=139262.
// y[m] = (2/N2) Re sum_{k=0}^{K-1} c_k X_k H_k e^{2pi i k m/N2}, c_0=c_{K-1}=1/2.
// X,H are DFT_{N1}; computed via Bluestein chirp-Z on pow2 FFTs (M1=2^18, M2=2^17),
// inverse sum is another chirp-Z at N2 on M1.
// Scratch: exactly two NCH*M1 ping-pong buffers; the h chain (M2-sized) aliases
// into bufB (2*NCH*M2 == NCH*M1), and the spectral combine is done in-place in bufA.

#define LX 131072
#define LH 8192
#define KK 69632            // rfft bins: 139263//2 + 1
#define M1 262144           // 2^18 >= LX+KK-1 = 200703
#define M2 131072           // 2^17 >= LH+KK-1 = 77823
#define NCH 64
#define NN1 139263LL
#define NN2 139262LL
#define PI_D 3.14159265358979323846264338327950288

// ------------------------- device scratch (no runtime alloc) ----------------
__device__ float2 g_bufA[(size_t)NCH * M1];
__device__ float2 g_bufB[(size_t)NCH * M1];   // also hosts h1/h2 (each NCH*M2)
__device__ float2 g_B1f[M1];     // FFT_M1 of chirp b (N1), wrapped
__device__ float2 g_Df[M1];      // FFT_M1 of chirp d (N2), wrapped
__device__ float2 g_B1fh[M2];    // FFT_M2 of chirp b (N1), wrapped
__device__ float2 g_T512[512];   // W_512^j
__device__ float2 g_TM1[512];    // W_{2^18}^j, j<512
__device__ float2 g_TM2[512];    // W_{2^17}^j, j<512

__device__ __forceinline__ float2 cmul(float2 a, float2 b) {
    return make_float2(a.x * b.x - a.y * b.y, a.x * b.y + a.y * b.x);
}

// e^{sgn * i*pi*u^2 / nmod} with exact integer phase reduction
__device__ __forceinline__ float2 chirp(long long u, long long nmod, float sgn) {
    const long long r = (u * u) % (2LL * nmod);
    const float ang = (float)((double)r * (PI_D / (double)nmod));
    float s, c;
    sincosf(ang, &s, &c);
    return make_float2(c, sgn * s);
}

// ------------------------- twiddle tables ------------------------------------
__global__ void k_tables() {
    const int j = threadIdx.x;  // 512 threads
    const double a = -2.0 * PI_D * (double)j;
    double s, c;
    sincos(a / 512.0, &s, &c);        g_T512[j] = make_float2((float)c, (float)s);
    sincos(a / (double)M1, &s, &c);   g_TM1[j]  = make_float2((float)c, (float)s);
    sincos(a / (double)M2, &s, &c);   g_TM2[j]  = make_float2((float)c, (float)s);
}

// ------------------------- Stockham radix-2 block FFT ------------------------
// 4 independent length-LEN FFTs per 256-thread block (64 lanes each).
// Natural order in, natural order out (autosort), ping-pong A<->B.
template <int LEN, bool INV>
__device__ float2* block_fft(float2* A, float2* B, const float2* tw, int tid) {
    const int g = tid >> 6, lane = tid & 63;
    const int go = g * LEN;
    float2* s = A;
    float2* d = B;
    int l2n = (LEN == 512) ? 9 : 8;   // log2 of current sub-size n
    int l2s = 0;
    for (int n = LEN; n >= 2; n >>= 1) {
#pragma unroll 4
        for (int bf = lane; bf < (LEN >> 1); bf += 64) {
            const int p = bf >> l2s;
            const int q = bf & ((1 << l2s) - 1);
            const float2 a = s[go + bf];
            const float2 b = s[go + bf + (LEN >> 1)];
            float2 w = tw[p << (9 - l2n)];   // W_n^p = W_512^{p*(512/n)}
            if (INV) w.y = -w.y;
            const float2 su = make_float2(a.x + b.x, a.y + b.y);
            const float2 df = make_float2(a.x - b.x, a.y - b.y);
            d[go + 2 * bf - q] = su;                          // q + s*2p
            d[go + 2 * bf - q + (1 << l2s)] = cmul(df, w);    // q + s*(2p+1)
        }
        __syncthreads();
        float2* t = s; s = d; d = t;
        l2n--; l2s++;
    }
    return s;
}

// ------------------------- four-step FFT passes ------------------------------
// M = NA * 512. n = n1 + NA*n2, k = k2 + 512*k1.
// pass1: FFT_512 over n2 for 4 columns n1; twiddle W_M^{n1*k2}; write transposed
//        tmp[k2*NA + n1]. Optional elementwise multiply of the INPUT by mulF
//        (used to fuse the chirp-filter spectrum into the conv-IFFT's 1st pass).
template <int MSZ, int NA, bool INV>
__global__ void __launch_bounds__(256) k_pass1(const float2* __restrict__ in,
                                               const float2* __restrict__ mulF,
                                               float2* __restrict__ out) {
    __shared__ float2 sA[4 * 512], sB[4 * 512], tw[512];
    const int tid = threadIdx.x;
    in  += (size_t)blockIdx.y * MSZ;
    out += (size_t)blockIdx.y * MSZ;
    const int colbase = blockIdx.x * 4;
    for (int j = tid; j < 512; j += 256) tw[j] = g_T512[j];
    for (int i = tid; i < 4 * 512; i += 256) {
        const int c = i & 3, t = i >> 2;
        const int idx = (colbase + c) + NA * t;
        float2 v = in[idx];
        if (mulF) v = cmul(v, mulF[idx]);
        sA[c * 512 + t] = v;
    }
    __syncthreads();
    float2* res = block_fft<512, INV>(sA, sB, tw, tid);
    constexpr int HS = (512 * 512) / MSZ;            // 1 (M1) or 2 (M2)
    const float2* lo = (MSZ == M1) ? g_TM1 : g_TM2;
    for (int i = tid; i < 4 * 512; i += 256) {
        const int c = i & 3, k2 = i >> 2;
        const int col = colbase + c;
        const unsigned a = (unsigned)(col * k2);     // < MSZ
        float2 w = cmul(g_T512[(a >> 9) * HS], lo[a & 511]);
        if (INV) w.y = -w.y;
        out[(size_t)k2 * NA + col] = cmul(res[c * 512 + k2], w);
    }
}

// pass2: FFT_NA over n1 for 4 rows k2; write X[k2 + 512*k1] (natural order).
template <int MSZ, int NA, bool INV>
__global__ void __launch_bounds__(256) k_pass2(const float2* __restrict__ in,
                                               float2* __restrict__ out) {
    __shared__ float2 sA[4 * 512], sB[4 * 512], tw[512];
    const int tid = threadIdx.x;
    in  += (size_t)blockIdx.y * MSZ;
    out += (size_t)blockIdx.y * MSZ;
    const int rowbase = blockIdx.x * 4;
    constexpr int L2NA = (NA == 512) ? 9 : 8;
    for (int j = tid; j < 512; j += 256) tw[j] = g_T512[j];
    for (int i = tid; i < 4 * NA; i += 256) {
        const int c = i >> L2NA, n1 = i & (NA - 1);
        sA[c * NA + n1] = in[(size_t)(rowbase + c) * NA + n1];
    }
    __syncthreads();
    float2* res = block_fft<NA, INV>(sA, sB, tw, tid);
    for (int i = tid; i < 4 * NA; i += 256) {
        const int c = i & 3, k1 = i >> 2;
        out[(size_t)(rowbase + c) + 512 * k1] = res[c * NA + k1];
    }
}

// ------------------------- pointwise kernels ---------------------------------
__global__ void k_prep_x(const float* __restrict__ x, float2* __restrict__ A) {
    const int i = blockIdx.x * 256 + threadIdx.x;   // < M1
    const int ch = blockIdx.y;
    float2 v = make_float2(0.f, 0.f);
    if (i < LX) {
        const float xv = x[(size_t)ch * LX + i];
        const float2 cc = chirp(i, NN1, -1.f);      // e^{-i pi n^2/N1}
        v = make_float2(xv * cc.x, xv * cc.y);
    }
    A[(size_t)ch * M1 + i] = v;
}

__global__ void k_prep_h(const float* __restrict__ h, float2* __restrict__ A) {
    const int i = blockIdx.x * 256 + threadIdx.x;   // < M2
    const int ch = blockIdx.y;
    float2 v = make_float2(0.f, 0.f);
    if (i < LH) {
        const float hv = h[(size_t)ch * LH + i];
        const float2 cc = chirp(i, NN1, -1.f);
        v = make_float2(hv * cc.x, hv * cc.y);
    }
    A[(size_t)ch * M2 + i] = v;
}

// b_m = e^{+i pi m^2/N1}; support m in [0,KK-1] and wrapped m in [1,LX-1]
__global__ void k_build_B1(float2* __restrict__ B) {
    const int i = blockIdx.x * 256 + threadIdx.x;   // < M1
    float2 v = make_float2(0.f, 0.f);
    if (i < KK)                    v = chirp(i, NN1, 1.f);
    else if (i >= M1 - LX + 1)     v = chirp((long long)(M1 - i), NN1, 1.f);
    B[i] = v;
}

__global__ void k_build_B1h(float2* __restrict__ B) {
    const int i = blockIdx.x * 256 + threadIdx.x;   // < M2
    float2 v = make_float2(0.f, 0.f);
    if (i < KK)                    v = chirp(i, NN1, 1.f);
    else if (i >= M2 - LH + 1)     v = chirp((long long)(M2 - i), NN1, 1.f);
    B[i] = v;
}

// d_j = e^{-i pi j^2/N2}; support j in [0,LX-1] and wrapped j in [1,KK-1]
__global__ void k_build_D(float2* __restrict__ D) {
    const int i = blockIdx.x * 256 + threadIdx.x;   // < M1
    float2 v = make_float2(0.f, 0.f);
    if (i < LX)                    v = chirp(i, NN2, -1.f);
    else if (i >= M1 - KK + 1)     v = chirp((long long)(M1 - i), NN2, -1.f);
    D[i] = v;
}

// In-place combine: U_k = c_k * X_k * H_k * e^{-i pi k^2/N1}*e^{-i pi k^2/N1}
// ... i.e. X_k = e^{-i pi k^2/N1}*Xc_k/M1, H_k = e^{-i pi k^2/N1}*Hc_k/M2, then
// U_k = c_k X_k H_k e^{+i pi k^2/N2}. Scales folded: 2/(N2*M1*M2).
// Reads Xc from U's own buffer (same element) -> in-place safe.
__global__ void k_combine(float2* __restrict__ U, const float2* __restrict__ Hc) {
    const int k = blockIdx.x * 256 + threadIdx.x;   // < M1
    const int ch = blockIdx.y;
    float2 v = make_float2(0.f, 0.f);
    if (k < KK) {
        const float2 xv = U[(size_t)ch * M1 + k];
        const float2 hv = Hc[(size_t)ch * M2 + k];
        const long long kk = (long long)k * k;
        const long long r1 = (2LL * kk) % (2LL * NN1);
        const long long r2 = kk % (2LL * NN2);
        const double ang = -(double)r1 * (PI_D / (double)NN1)
                           + (double)r2 * (PI_D / (double)NN2);
        float sn, cs;
        sincosf((float)ang, &sn, &cs);
        float2 t = cmul(xv, hv);
        t = cmul(t, make_float2(cs, sn));
        float sc = (float)(2.0 / ((double)NN2 * (double)M1 * (double)M2));
        if (k == 0 || k == KK - 1) sc *= 0.5f;
        v = make_float2(t.x * sc, t.y * sc);
    }
    U[(size_t)ch * M1 + k] = v;
}

// y[m] = Re{ S_m * e^{+i pi m^2/N2} } / M1
__global__ void k_final(const float2* __restrict__ S, float* __restrict__ y) {
    const int m = blockIdx.x * 256 + threadIdx.x;   // < LX
    const int ch = blockIdx.y;
    const float2 sv = S[(size_t)ch * M1 + m];
    const float2 ph = chirp(m, NN2, 1.f);
    y[(size_t)ch * LX + m] = (sv.x * ph.x - sv.y * ph.y) * (1.0f / (float)M1);
}

// ------------------------- launcher ------------------------------------------
extern "C" void kernel_launch(void* const* d_in, const int* in_sizes, int n_in,
                              void* d_out, int out_size) {
    const float* x = (const float*)d_in[0];   // [32,2,131072]
    const float* h = (const float*)d_in[1];   // [32,2,8192]
    float* y = (float*)d_out;

    float2 *bufA, *bufB, *B1f, *Df, *B1fh;
    cudaGetSymbolAddress((void**)&bufA, g_bufA);
    cudaGetSymbolAddress((void**)&bufB, g_bufB);
    cudaGetSymbolAddress((void**)&B1f,  g_B1f);
    cudaGetSymbolAddress((void**)&Df,   g_Df);
    cudaGetSymbolAddress((void**)&B1fh, g_B1fh);
    float2* h1 = bufB;                         // NCH*M2
    float2* h2 = bufB + (size_t)NCH * M2;      // NCH*M2 (2*NCH*M2 == NCH*M1)

    k_tables<<<1, 512>>>();

    // --- precompute chirp-filter spectra (batch 1, uses bufA/bufB as tmp) ---
    k_build_B1<<<M1 / 256, 256>>>(bufA);
    k_pass1<M1, 512, false><<<dim3(128, 1), 256>>>(bufA, nullptr, bufB);
    k_pass2<M1, 512, false><<<dim3(128, 1), 256>>>(bufB, B1f);

    k_build_D<<<M1 / 256, 256>>>(bufA);
    k_pass1<M1, 512, false><<<dim3(128, 1), 256>>>(bufA, nullptr, bufB);
    k_pass2<M1, 512, false><<<dim3(128, 1), 256>>>(bufB, Df);

    k_build_B1h<<<M2 / 256, 256>>>(bufA);
    k_pass1<M2, 256, false><<<dim3(64, 1), 256>>>(bufA, nullptr, bufB);
    k_pass2<M2, 256, false><<<dim3(128, 1), 256>>>(bufB, B1fh);

    // --- x chain: chirp-Z forward DFT_N1, bins 0..KK-1; result -> bufA ---
    k_prep_x<<<dim3(M1 / 256, NCH), 256>>>(x, bufA);
    k_pass1<M1, 512, false><<<dim3(128, NCH), 256>>>(bufA, nullptr, bufB);
    k_pass2<M1, 512, false><<<dim3(128, NCH), 256>>>(bufB, bufA);
    k_pass1<M1, 512, true ><<<dim3(128, NCH), 256>>>(bufA, B1f, bufB);   // fused *B1f
    k_pass2<M1, 512, true ><<<dim3(128, NCH), 256>>>(bufB, bufA);

    // --- h chain inside bufB (bufA holds X, untouched); result -> h1 ---
    k_prep_h<<<dim3(M2 / 256, NCH), 256>>>(h, h1);
    k_pass1<M2, 256, false><<<dim3(64, NCH), 256>>>(h1, nullptr, h2);
    k_pass2<M2, 256, false><<<dim3(128, NCH), 256>>>(h2, h1);
    k_pass1<M2, 256, true ><<<dim3(64, NCH), 256>>>(h1, B1fh, h2);       // fused *B1fh
    k_pass2<M2, 256, true ><<<dim3(128, NCH), 256>>>(h2, h1);

    // --- combine in-place into bufA, then inverse chirp-Z at N2 ---
    k_combine<<<dim3(M1 / 256, NCH), 256>>>(bufA, h1);
    k_pass1<M1, 512, false><<<dim3(128, NCH), 256>>>(bufA, nullptr, bufB);
    k_pass2<M1, 512, false><<<dim3(128, NCH), 256>>>(bufB, bufA);
    k_pass1<M1, 512, true ><<<dim3(128, NCH), 256>>>(bufA, Df, bufB);    // fused *Df
    k_pass2<M1, 512, true ><<<dim3(128, NCH), 256>>>(bufB, bufA);

    k_final<<<dim3(LX / 256, NCH), 256>>>(bufA, y);
}

// round 6
// speedup vs baseline: 1.4596x; 1.4596x over previous
#include <cuda_runtime.h>
#include <math.h>

// y = irfft(rfft(x, n=139263) * rfft(h, n=139263))[..., :131072]
// rfft grid N1=139263 (odd), irfft default grid N2=139262.
// y[m] = (2/N2) Re sum_{k<K} c_k X_k H_k e^{2pi i k m/N2}, c_0=c_{K-1}=1/2.
// Bluestein chirp-Z on pow2 FFTs (M1=2^18 for x & inverse, M2=2^17 for h).
// Fused pipeline: every P2->pointwise->P1 triple is one kernel; radix-4 Stockham.

#define LX 131072
#define LH 8192
#define KK 69632
#define M1 262144
#define M2 131072
#define NCH 64
#define NN1 139263LL
#define NN2 139262LL
#define PI_D 3.14159265358979323846264338327950288

__device__ float2 g_bufA[(size_t)NCH * M1];
__device__ float2 g_bufB[(size_t)NCH * M1];
__device__ float2 g_bufH[(size_t)NCH * M2];
__device__ float2 g_B1f[M1];
__device__ float2 g_Df[M1];
__device__ float2 g_B1fh[M2];
__device__ float2 g_T512[512];
__device__ float2 g_TM1[512];
__device__ float2 g_TM2[512];

__device__ __forceinline__ float2 cmul(float2 a, float2 b) {
    return make_float2(a.x * b.x - a.y * b.y, a.x * b.y + a.y * b.x);
}
__device__ __forceinline__ float2 cadd(float2 a, float2 b) {
    return make_float2(a.x + b.x, a.y + b.y);
}
__device__ __forceinline__ float2 csub(float2 a, float2 b) {
    return make_float2(a.x - b.x, a.y - b.y);
}
__device__ __forceinline__ float2 chirp(long long u, long long nmod, float sgn) {
    const long long r = (u * u) % (2LL * nmod);
    const float ang = (float)((double)r * (PI_D / (double)nmod));
    float s, c;
    sincosf(ang, &s, &c);
    return make_float2(c, sgn * s);
}

__global__ void k_tables() {
    const int j = threadIdx.x;
    const double a = -2.0 * PI_D * (double)j;
    double s, c;
    sincos(a / 512.0, &s, &c);       g_T512[j] = make_float2((float)c, (float)s);
    sincos(a / (double)M1, &s, &c);  g_TM1[j]  = make_float2((float)c, (float)s);
    sincos(a / (double)M2, &s, &c);  g_TM2[j]  = make_float2((float)c, (float)s);
}

// ---------------- radix-4 Stockham block FFT (final radix-2 if log2 odd) ----
// NFFT transforms of length LEN in SMEM, 256 threads, ping-pong A<->B.
template <int LEN, int NFFT, bool INV>
__device__ float2* block_fft4(float2* A, float2* B, const float2* tw, int tid) {
    constexpr int LPF = 256 / NFFT;
    const int g = tid / LPF, lane = tid % LPF;
    const int go = g * LEN;
    float2 *s = A, *d = B;
    int l2n = (LEN == 512) ? 9 : 8;
    int l2s = 0;
    int n = LEN;
    while (n >= 4) {
        for (int bf = lane; bf < LEN / 4; bf += LPF) {
            const int p = bf >> l2s;
            const int q = bf & ((1 << l2s) - 1);
            const float2 Aa = s[go + bf];
            const float2 Bb = s[go + bf + LEN / 4];
            const float2 Cc = s[go + bf + LEN / 2];
            const float2 Dd = s[go + bf + 3 * LEN / 4];
            float2 w1 = tw[p << (9 - l2n)];
            float2 w2 = tw[(2 * p) << (9 - l2n)];
            float2 w3 = tw[(3 * p) << (9 - l2n)];
            if (INV) { w1.y = -w1.y; w2.y = -w2.y; w3.y = -w3.y; }
            const float2 s0 = cadd(Aa, Cc), d0 = csub(Aa, Cc);
            const float2 s1 = cadd(Bb, Dd), d1 = csub(Bb, Dd);
            const float2 e = INV ? make_float2(-d1.y, d1.x)
                                 : make_float2(d1.y, -d1.x);
            const int ob = q + (p << (l2s + 2));
            const int ss = 1 << l2s;
            d[go + ob]          = cadd(s0, s1);
            d[go + ob + ss]     = cmul(w1, cadd(d0, e));
            d[go + ob + 2 * ss] = cmul(w2, csub(s0, s1));
            d[go + ob + 3 * ss] = cmul(w3, csub(d0, e));
        }
        __syncthreads();
        float2* t = s; s = d; d = t;
        l2n -= 2; l2s += 2; n >>= 2;
    }
    if (n == 2) {
        for (int bf = lane; bf < LEN / 2; bf += LPF) {
            const float2 a = s[go + bf], b = s[go + bf + LEN / 2];
            d[go + bf] = cadd(a, b);
            d[go + bf + LEN / 2] = csub(a, b);
        }
        __syncthreads();
        float2* t = s; s = d; d = t;
    }
    return s;
}

// composite twiddle W_MSZ^a
template <int MSZ>
__device__ __forceinline__ float2 wM(unsigned a, bool conj) {
    constexpr int HS = (512 * 512) / MSZ;
    const float2* lo = (MSZ == M1) ? g_TM1 : g_TM2;
    float2 w = cmul(g_T512[(a >> 9) * HS], lo[a & 511]);
    if (conj) w.y = -w.y;
    return w;
}

// ---------------- pass1 with generated input --------------------------------
// MODE: 0=load_x, 1=load_h, 2=gen_B1 (M1), 3=gen_D (M1), 4=gen_B1h (M2)
template <int MSZ, int NA, int MODE>
__global__ void __launch_bounds__(256) k_pass1g(const float* __restrict__ src,
                                                float2* __restrict__ out) {
    __shared__ float2 sA[2048], sB[2048], tw[512];
    const int tid = threadIdx.x;
    const int ch = blockIdx.y;
    out += (size_t)ch * MSZ;
    const int colbase = blockIdx.x * 4;
    for (int j = tid; j < 512; j += 256) tw[j] = g_T512[j];
    for (int i = tid; i < 4 * 512; i += 256) {
        const int c = i & 3, t = i >> 2;
        const int n = (colbase + c) + NA * t;
        float2 v = make_float2(0.f, 0.f);
        if (MODE == 0) {
            if (n < LX) {
                const float xv = src[(size_t)ch * LX + n];
                const float2 cc = chirp(n, NN1, -1.f);
                v = make_float2(xv * cc.x, xv * cc.y);
            }
        } else if (MODE == 1) {
            if (n < LH) {
                const float hv = src[(size_t)ch * LH + n];
                const float2 cc = chirp(n, NN1, -1.f);
                v = make_float2(hv * cc.x, hv * cc.y);
            }
        } else if (MODE == 2) {
            if (n < KK)                 v = chirp(n, NN1, 1.f);
            else if (n >= M1 - LX + 1)  v = chirp((long long)(M1 - n), NN1, 1.f);
        } else if (MODE == 3) {
            if (n < LX)                 v = chirp(n, NN2, -1.f);
            else if (n >= M1 - KK + 1)  v = chirp((long long)(M1 - n), NN2, -1.f);
        } else {
            if (n < KK)                 v = chirp(n, NN1, 1.f);
            else if (n >= M2 - LH + 1)  v = chirp((long long)(M2 - n), NN1, 1.f);
        }
        sA[c * 512 + t] = v;
    }
    __syncthreads();
    float2* res = block_fft4<512, 4, false>(sA, sB, tw, tid);
    for (int i = tid; i < 4 * 512; i += 256) {
        const int c = i & 3, k2 = i >> 2;
        const int col = colbase + c;
        out[(size_t)k2 * NA + col] =
            cmul(res[c * 512 + k2], wM<MSZ>((unsigned)(col * k2), false));
    }
}

// ---------------- plain pass2 ------------------------------------------------
template <int MSZ, int NA, bool INV>
__global__ void __launch_bounds__(256) k_pass2(const float2* __restrict__ in,
                                               float2* __restrict__ out) {
    __shared__ float2 sA[2048], sB[2048], tw[512];
    const int tid = threadIdx.x;
    in  += (size_t)blockIdx.y * MSZ;
    out += (size_t)blockIdx.y * MSZ;
    const int rowbase = blockIdx.x * 4;
    for (int j = tid; j < 512; j += 256) tw[j] = g_T512[j];
    for (int i = tid; i < 4 * NA; i += 256) {
        const int c = i / NA, n1 = i % NA;
        sA[c * NA + n1] = in[(size_t)(rowbase + c) * NA + n1];
    }
    __syncthreads();
    float2* res = block_fft4<NA, 4, INV>(sA, sB, tw, tid);
    constexpr int NROW = MSZ / NA;
    for (int i = tid; i < 4 * NA; i += 256) {
        const int c = i & 3, k1 = i >> 2;
        out[(size_t)(rowbase + c) + NROW * k1] = res[c * NA + k1];
    }
}

// ---------------- fused M1 kernel: P2(dir1) + pointwise + P1(dir2) ----------
// PW=0: fwd, *B1f, inv | PW=1: inv, combine(Hc), fwd | PW=2: fwd, *Df, inv
template <int PW>
__global__ void __launch_bounds__(256) k_fusedM1(const float2* __restrict__ in,
                                                 const float2* __restrict__ filt,
                                                 const float2* __restrict__ Hc,
                                                 float2* __restrict__ out) {
    __shared__ float2 sA[2048], sB[2048], tw[512];
    const int tid = threadIdx.x;
    const int ch = blockIdx.y;
    in  += (size_t)ch * M1;
    out += (size_t)ch * M1;
    const int rowbase = blockIdx.x * 4;
    for (int j = tid; j < 512; j += 256) tw[j] = g_T512[j];
    for (int i = tid; i < 2048; i += 256) {
        const int c = i >> 9, n1 = i & 511;
        sA[c * 512 + n1] = in[(size_t)(rowbase + c) * 512 + n1];
    }
    __syncthreads();
    constexpr bool D1 = (PW == 1);   // dir1 inverse?
    float2* r1 = block_fft4<512, 4, D1>(sA, sB, tw, tid);
    float2* other = (r1 == sA) ? sB : sA;
    for (int i = tid; i < 2048; i += 256) {
        const int c = i & 3, k1 = i >> 2;
        const int k = (rowbase + c) + 512 * k1;
        const float2 xv = r1[c * 512 + k1];
        float2 v;
        if (PW == 1) {
            v = make_float2(0.f, 0.f);
            if (k < KK) {
                const float2 hv = Hc[(size_t)ch * M2 + k];
                const long long kk = (long long)k * k;
                const long long ra = (2LL * kk) % (2LL * NN1);
                const long long rb = kk % (2LL * NN2);
                const double ang = -(double)ra * (PI_D / (double)NN1)
                                   + (double)rb * (PI_D / (double)NN2);
                float sn, cs;
                sincosf((float)ang, &sn, &cs);
                float2 t = cmul(xv, hv);
                t = cmul(t, make_float2(cs, sn));
                float sc = (float)(2.0 / ((double)NN2 * (double)M1 * (double)M2));
                if (k == 0 || k == KK - 1) sc *= 0.5f;
                v = make_float2(t.x * sc, t.y * sc);
            }
        } else {
            v = cmul(xv, filt[k]);
        }
        other[c * 512 + k1] = v;
    }
    __syncthreads();
    constexpr bool D2 = (PW != 1);   // dir2 inverse?
    float2* r2 = block_fft4<512, 4, D2>(other, (other == sA) ? sB : sA, tw, tid);
    for (int i = tid; i < 2048; i += 256) {
        const int c = i & 3, k2p = i >> 2;
        const int col = rowbase + c;
        out[(size_t)k2p * 512 + col] =
            cmul(r2[c * 512 + k2p], wM<M1>((unsigned)(col * k2p), D2));
    }
}

// ---------------- fused M2 kernel: P2(fwd) + *B1fh + P1(inv) ----------------
// Block owns rows {r, r+1, r+256, r+257} (r = 2*bx) == P1inv columns {r, r+1}.
__global__ void __launch_bounds__(256) k_fusedM2(const float2* __restrict__ in,
                                                 const float2* __restrict__ filt,
                                                 float2* __restrict__ out) {
    __shared__ float2 sA[2048], sB[2048], tw[512];
    const int tid = threadIdx.x;
    const int ch = blockIdx.y;
    in  += (size_t)ch * M2;
    out += (size_t)ch * M2;
    const int r = blockIdx.x * 2;
    for (int j = tid; j < 512; j += 256) tw[j] = g_T512[j];
    // rows4[c] = r + (c&1) + 256*(c>>1)
    for (int i = tid; i < 1024; i += 256) {
        const int c = i >> 8, n1 = i & 255;
        const int row = r + (c & 1) + 256 * (c >> 1);
        sA[c * 256 + n1] = in[(size_t)row * 256 + n1];
    }
    __syncthreads();
    float2* r1 = block_fft4<256, 4, false>(sA, sB, tw, tid);
    float2* other = (r1 == sA) ? sB : sA;
    // reorg + filter: S[c0*512 + n2] = r1[(2*hi + c0)*256 + k1] * filt[k],
    // n2 = 2*k1 + hi, k = (r + c0 + 256*hi) + 512*k1
    for (int i = tid; i < 1024; i += 256) {
        const int c0 = i & 1, n2 = i >> 1;
        const int k1 = n2 >> 1, hi = n2 & 1;
        const int k = (r + c0 + 256 * hi) + 512 * k1;
        other[c0 * 512 + n2] = cmul(r1[(2 * hi + c0) * 256 + k1], filt[k]);
    }
    __syncthreads();
    float2* r2 = block_fft4<512, 2, true>(other, (other == sA) ? sB : sA, tw, tid);
    for (int i = tid; i < 1024; i += 256) {
        const int c0 = i & 1, k2p = i >> 1;
        const int col = r + c0;
        out[(size_t)k2p * 256 + col] =
            cmul(r2[c0 * 512 + k2p], wM<M2>((unsigned)(col * k2p), true));
    }
}

// ---------------- final output ----------------------------------------------
__global__ void k_final(const float2* __restrict__ S, float* __restrict__ y) {
    const int m = blockIdx.x * 256 + threadIdx.x;
    const int ch = blockIdx.y;
    const float2 sv = S[(size_t)ch * M1 + m];
    const float2 ph = chirp(m, NN2, 1.f);
    y[(size_t)ch * LX + m] = (sv.x * ph.x - sv.y * ph.y) * (1.0f / (float)M1);
}

// ---------------- launcher ---------------------------------------------------
extern "C" void kernel_launch(void* const* d_in, const int* in_sizes, int n_in,
                              void* d_out, int out_size) {
    const float* x = (const float*)d_in[0];
    const float* h = (const float*)d_in[1];
    float* y = (float*)d_out;

    float2 *bufA, *bufB, *bufH, *B1f, *Df, *B1fh;
    cudaGetSymbolAddress((void**)&bufA, g_bufA);
    cudaGetSymbolAddress((void**)&bufB, g_bufB);
    cudaGetSymbolAddress((void**)&bufH, g_bufH);
    cudaGetSymbolAddress((void**)&B1f,  g_B1f);
    cudaGetSymbolAddress((void**)&Df,   g_Df);
    cudaGetSymbolAddress((void**)&B1fh, g_B1fh);
    float2* hs1 = bufA;
    float2* hs2 = bufA + (size_t)NCH * M2;

    k_tables<<<1, 512>>>();

    // filter spectra (batch 1)
    k_pass1g<M1, 512, 2><<<dim3(128, 1), 256>>>(nullptr, bufB);
    k_pass2<M1, 512, false><<<dim3(128, 1), 256>>>(bufB, B1f);
    k_pass1g<M1, 512, 3><<<dim3(128, 1), 256>>>(nullptr, bufB);
    k_pass2<M1, 512, false><<<dim3(128, 1), 256>>>(bufB, Df);
    k_pass1g<M2, 256, 4><<<dim3(64, 1), 256>>>(nullptr, bufB);
    k_pass2<M2, 256, false><<<dim3(128, 1), 256>>>(bufB, B1fh);

    // h chain -> bufH (natural-order H spectrum factor)
    k_pass1g<M2, 256, 1><<<dim3(64, NCH), 256>>>(h, hs1);
    k_fusedM2<<<dim3(128, NCH), 256>>>(hs1, B1fh, hs2);
    k_pass2<M2, 256, true><<<dim3(128, NCH), 256>>>(hs2, bufH);

    // x chain + combine + inverse chirp-Z
    k_pass1g<M1, 512, 0><<<dim3(128, NCH), 256>>>(x, bufB);
    k_fusedM1<0><<<dim3(128, NCH), 256>>>(bufB, B1f, nullptr, bufA);
    k_fusedM1<1><<<dim3(128, NCH), 256>>>(bufA, nullptr, bufH, bufB);
    k_fusedM1<2><<<dim3(128, NCH), 256>>>(bufB, Df, nullptr, bufA);
    k_pass2<M1, 512, true><<<dim3(128, NCH), 256>>>(bufA, bufB);
    k_final<<<dim3(LX / 256, NCH), 256>>>(bufB, y);
}

// round 9
// speedup vs baseline: 1.8663x; 1.2786x over previous
#include <cuda_runtime.h>
#include <math.h>

// y = irfft(rfft(x, n=139263) * rfft(h, n=139263))[..., :131072]
// rfft grid N1=139263 (odd), irfft default grid N2=139262.
// y[m] = (2/N2) Re sum_{k<K} c_k X_k H_k e^{2pi i k m/N2}, c_0=c_{K-1}=1/2.
// Bluestein chirp-Z on pow2 FFTs (M1=2^18 for x & inverse, M2=2^17 for h).
// Radix-8 Stockham in swizzled SMEM; every P2->pointwise->P1 triple fused. v2.

#define LX 131072
#define LH 8192
#define KK 69632
#define M1 262144
#define M2 131072
#define NCH 64
#define NN1 139263LL
#define NN2 139262LL
#define PI_D 3.14159265358979323846264338327950288

__device__ float2 g_bufA[(size_t)NCH * M1];
__device__ float2 g_bufB[(size_t)NCH * M1];
__device__ float2 g_bufH[(size_t)NCH * M2];
__device__ float2 g_FM1[2 * M1];   // [0]=B1f spectrum, [1]=Df spectrum
__device__ float2 g_B1fh[M2];
__device__ float2 g_T512[512];
__device__ float2 g_TM1[512];
__device__ float2 g_TM2[512];

__device__ __forceinline__ float2 cmul(float2 a, float2 b) {
    return make_float2(a.x * b.x - a.y * b.y, a.x * b.y + a.y * b.x);
}
__device__ __forceinline__ float2 cadd(float2 a, float2 b) {
    return make_float2(a.x + b.x, a.y + b.y);
}
__device__ __forceinline__ float2 csub(float2 a, float2 b) {
    return make_float2(a.x - b.x, a.y - b.y);
}
__device__ __forceinline__ float2 chirp(long long u, long long nmod, float sgn) {
    const long long r = (u * u) % (2LL * nmod);
    const float ang = (float)((double)r * (PI_D / (double)nmod));
    float s, c;
    sincosf(ang, &s, &c);
    return make_float2(c, sgn * s);
}
// SMEM bank swizzle: XORs bits 4..7 into bits 0..3; bijective per 16-group.
__device__ __forceinline__ int sw(int i) { return i ^ ((i >> 4) & 15); }

__global__ void k_tables() {
    const int j = threadIdx.x;
    const double a = -2.0 * PI_D * (double)j;
    double s, c;
    sincos(a / 512.0, &s, &c);       g_T512[j] = make_float2((float)c, (float)s);
    sincos(a / (double)M1, &s, &c);  g_TM1[j]  = make_float2((float)c, (float)s);
    sincos(a / (double)M2, &s, &c);  g_TM2[j]  = make_float2((float)c, (float)s);
}

// ---------------- register butterflies ---------------------------------------
template <bool INV>
__device__ __forceinline__ void dft4(float2& a, float2& b, float2& c, float2& d) {
    const float2 t0 = cadd(a, c), t1 = csub(a, c);
    const float2 t2 = cadd(b, d), t3 = csub(b, d);
    const float2 r = INV ? make_float2(-t3.y, t3.x) : make_float2(t3.y, -t3.x);
    a = cadd(t0, t2); b = cadd(t1, r); c = csub(t0, t2); d = csub(t1, r);
}
template <bool INV>
__device__ __forceinline__ void dft8(float2 v[8]) {
    float2 e0 = v[0], e1 = v[2], e2 = v[4], e3 = v[6];
    float2 o0 = v[1], o1 = v[3], o2 = v[5], o3 = v[7];
    dft4<INV>(e0, e1, e2, e3);
    dft4<INV>(o0, o1, o2, o3);
    const float r = 0.70710678118654752f;
    const float2 w1 = INV ? make_float2(r, r)  : make_float2(r, -r);
    const float2 w3 = INV ? make_float2(-r, r) : make_float2(-r, -r);
    o1 = cmul(o1, w1);
    o2 = INV ? make_float2(-o2.y, o2.x) : make_float2(o2.y, -o2.x);
    o3 = cmul(o3, w3);
    v[0] = cadd(e0, o0); v[4] = csub(e0, o0);
    v[1] = cadd(e1, o1); v[5] = csub(e1, o1);
    v[2] = cadd(e2, o2); v[6] = csub(e2, o2);
    v[3] = cadd(e3, o3); v[7] = csub(e3, o3);
}

// ---------------- radix-8 Stockham block FFT (r4/r2 tail) -------------------
// NFFT transforms of length LEN in swizzled SMEM, 256 threads, ping-pong.
template <int LEN, int NFFT, bool INV>
__device__ float2* block_fft8(float2* A, float2* B, const float2* tw, int tid) {
    constexpr int LPF = 256 / NFFT;
    const int g = tid / LPF, lane = tid % LPF;
    const int go = g * LEN;
    float2 *s = A, *d = B;
    int l2n = (LEN == 512) ? 9 : 8;
    int l2s = 0;
    int n = LEN;
    while (n >= 8) {
        for (int bf = lane; bf < LEN / 8; bf += LPF) {
            const int p = bf >> l2s;
            const int q = bf & ((1 << l2s) - 1);
            float2 v[8];
#pragma unroll
            for (int m = 0; m < 8; m++) v[m] = s[go + sw(bf + m * (LEN / 8))];
            dft8<INV>(v);
            const int ss = 1 << l2s;
            const int ob = q + (p << (l2s + 3));
            d[go + sw(ob)] = v[0];
#pragma unroll
            for (int m = 1; m < 8; m++) {
                float2 w = tw[(p * m) << (9 - l2n)];
                if (INV) w.y = -w.y;
                d[go + sw(ob + m * ss)] = cmul(w, v[m]);
            }
        }
        __syncthreads();
        float2* t = s; s = d; d = t;
        l2n -= 3; l2s += 3; n >>= 3;
    }
    if (n == 4) {
        for (int bf = lane; bf < LEN / 4; bf += LPF) {
            const int p = bf >> l2s;
            const int q = bf & ((1 << l2s) - 1);
            float2 a = s[go + sw(bf)];
            float2 b = s[go + sw(bf + LEN / 4)];
            float2 c = s[go + sw(bf + LEN / 2)];
            float2 e = s[go + sw(bf + 3 * LEN / 4)];
            dft4<INV>(a, b, c, e);
            const int ss = 1 << l2s;
            const int ob = q + (p << (l2s + 2));
            float2 w1 = tw[p << (9 - l2n)];
            float2 w2 = tw[(2 * p) << (9 - l2n)];
            float2 w3 = tw[(3 * p) << (9 - l2n)];
            if (INV) { w1.y = -w1.y; w2.y = -w2.y; w3.y = -w3.y; }
            d[go + sw(ob)] = a;
            d[go + sw(ob + ss)] = cmul(w1, b);
            d[go + sw(ob + 2 * ss)] = cmul(w2, c);
            d[go + sw(ob + 3 * ss)] = cmul(w3, e);
        }
        __syncthreads();
        float2* t = s; s = d; d = t;
    } else if (n == 2) {
        for (int bf = lane; bf < LEN / 2; bf += LPF) {
            const float2 a = s[go + sw(bf)], b = s[go + sw(bf + LEN / 2)];
            d[go + sw(bf)] = cadd(a, b);
            d[go + sw(bf + LEN / 2)] = csub(a, b);
        }
        __syncthreads();
        float2* t = s; s = d; d = t;
    }
    return s;
}

template <int MSZ>
__device__ __forceinline__ float2 wM(unsigned a, bool conj) {
    constexpr int HS = (512 * 512) / MSZ;
    const float2* lo = (MSZ == M1) ? g_TM1 : g_TM2;
    float2 w = cmul(g_T512[(a >> 9) * HS], lo[a & 511]);
    if (conj) w.y = -w.y;
    return w;
}

// ---------------- pass1 with generated input --------------------------------
// MODE: 0=load_x (M1), 1=load_h (M2), 4=gen_B1h (M2)
template <int MSZ, int NA, int MODE>
__global__ void __launch_bounds__(256) k_pass1g(const float* __restrict__ src,
                                                float2* __restrict__ out) {
    __shared__ float2 sA[2048], sB[2048], tw[512];
    const int tid = threadIdx.x;
    const int ch = blockIdx.y;
    out += (size_t)ch * MSZ;
    const int colbase = blockIdx.x * 4;
    for (int j = tid; j < 512; j += 256) tw[j] = g_T512[j];
    for (int i = tid; i < 4 * 512; i += 256) {
        const int c = i & 3, t = i >> 2;
        const int n = (colbase + c) + NA * t;
        float2 v = make_float2(0.f, 0.f);
        if (MODE == 0) {
            if (n < LX) {
                const float xv = src[(size_t)ch * LX + n];
                const float2 cc = chirp(n, NN1, -1.f);
                v = make_float2(xv * cc.x, xv * cc.y);
            }
        } else if (MODE == 1) {
            if (n < LH) {
                const float hv = src[(size_t)ch * LH + n];
                const float2 cc = chirp(n, NN1, -1.f);
                v = make_float2(hv * cc.x, hv * cc.y);
            }
        } else {
            if (n < KK)                 v = chirp(n, NN1, 1.f);
            else if (n >= M2 - LH + 1)  v = chirp((long long)(M2 - n), NN1, 1.f);
        }
        sA[sw(c * 512 + t)] = v;
    }
    __syncthreads();
    float2* res = block_fft8<512, 4, false>(sA, sB, tw, tid);
    for (int i = tid; i < 4 * 512; i += 256) {
        const int c = i & 3, k2 = i >> 2;
        const int col = colbase + c;
        out[(size_t)k2 * NA + col] =
            cmul(res[sw(c * 512 + k2)], wM<MSZ>((unsigned)(col * k2), false));
    }
}

// filter generator pass1 (M1): blockIdx.y: 0 -> chirp b (N1), 1 -> chirp d (N2)
__global__ void __launch_bounds__(256) k_pass1f(float2* __restrict__ out) {
    __shared__ float2 sA[2048], sB[2048], tw[512];
    const int tid = threadIdx.x;
    const int which = blockIdx.y;
    out += (size_t)which * M1;
    const int colbase = blockIdx.x * 4;
    for (int j = tid; j < 512; j += 256) tw[j] = g_T512[j];
    for (int i = tid; i < 4 * 512; i += 256) {
        const int c = i & 3, t = i >> 2;
        const int n = (colbase + c) + 512 * t;
        float2 v = make_float2(0.f, 0.f);
        if (which == 0) {
            if (n < KK)                 v = chirp(n, NN1, 1.f);
            else if (n >= M1 - LX + 1)  v = chirp((long long)(M1 - n), NN1, 1.f);
        } else {
            if (n < LX)                 v = chirp(n, NN2, -1.f);
            else if (n >= M1 - KK + 1)  v = chirp((long long)(M1 - n), NN2, -1.f);
        }
        sA[sw(c * 512 + t)] = v;
    }
    __syncthreads();
    float2* res = block_fft8<512, 4, false>(sA, sB, tw, tid);
    for (int i = tid; i < 4 * 512; i += 256) {
        const int c = i & 3, k2 = i >> 2;
        const int col = colbase + c;
        out[(size_t)k2 * 512 + col] =
            cmul(res[sw(c * 512 + k2)], wM<M1>((unsigned)(col * k2), false));
    }
}

// ---------------- plain pass2 ------------------------------------------------
template <int MSZ, int NA, bool INV>
__global__ void __launch_bounds__(256) k_pass2(const float2* __restrict__ in,
                                               float2* __restrict__ out) {
    __shared__ float2 sA[2048], sB[2048], tw[512];
    const int tid = threadIdx.x;
    in  += (size_t)blockIdx.y * MSZ;
    out += (size_t)blockIdx.y * MSZ;
    const int rowbase = blockIdx.x * 4;
    for (int j = tid; j < 512; j += 256) tw[j] = g_T512[j];
    for (int i = tid; i < 4 * NA; i += 256) {
        const int c = i / NA, n1 = i % NA;
        sA[sw(c * NA + n1)] = in[(size_t)(rowbase + c) * NA + n1];
    }
    __syncthreads();
    float2* res = block_fft8<NA, 4, INV>(sA, sB, tw, tid);
    constexpr int NROW = MSZ / NA;
    for (int i = tid; i < 4 * NA; i += 256) {
        const int c = i & 3, k1 = i >> 2;
        out[(size_t)(rowbase + c) + NROW * k1] = res[sw(c * NA + k1)];
    }
}

// pass2 (M1, inverse) fused with final chirp + real output ------------------
__global__ void __launch_bounds__(256) k_pass2f(const float2* __restrict__ in,
                                                float* __restrict__ y) {
    __shared__ float2 sA[2048], sB[2048], tw[512];
    const int tid = threadIdx.x;
    const int ch = blockIdx.y;
    in += (size_t)ch * M1;
    const int rowbase = blockIdx.x * 4;
    for (int j = tid; j < 512; j += 256) tw[j] = g_T512[j];
    for (int i = tid; i < 2048; i += 256) {
        const int c = i >> 9, n1 = i & 511;
        sA[sw(c * 512 + n1)] = in[(size_t)(rowbase + c) * 512 + n1];
    }
    __syncthreads();
    float2* res = block_fft8<512, 4, true>(sA, sB, tw, tid);
    constexpr float INVM1 = 1.0f / (float)M1;
    for (int i = tid; i < 2048; i += 256) {
        const int c = i & 3, k1 = i >> 2;
        const int m = (rowbase + c) + 512 * k1;
        if (m < LX) {
            const float2 sv = res[sw(c * 512 + k1)];
            const float2 ph = chirp(m, NN2, 1.f);
            y[(size_t)ch * LX + m] = (sv.x * ph.x - sv.y * ph.y) * INVM1;
        }
    }
}

// ---------------- fused M1 kernel: P2(dir1) + pointwise + P1(dir2) ----------
// PW=0: fwd, *B1f, inv | PW=1: inv, combine(Hc), fwd | PW=2: fwd, *Df, inv
template <int PW>
__global__ void __launch_bounds__(256) k_fusedM1(const float2* __restrict__ in,
                                                 const float2* __restrict__ filt,
                                                 const float2* __restrict__ Hc,
                                                 float2* __restrict__ out) {
    __shared__ float2 sA[2048], sB[2048], tw[512];
    const int tid = threadIdx.x;
    const int ch = blockIdx.y;
    in  += (size_t)ch * M1;
    out += (size_t)ch * M1;
    const int rowbase = blockIdx.x * 4;
    for (int j = tid; j < 512; j += 256) tw[j] = g_T512[j];
    for (int i = tid; i < 2048; i += 256) {
        const int c = i >> 9, n1 = i & 511;
        sA[sw(c * 512 + n1)] = in[(size_t)(rowbase + c) * 512 + n1];
    }
    __syncthreads();
    constexpr bool D1 = (PW == 1);
    float2* r1 = block_fft8<512, 4, D1>(sA, sB, tw, tid);
    float2* other = (r1 == sA) ? sB : sA;
    for (int i = tid; i < 2048; i += 256) {
        const int c = i & 3, k1 = i >> 2;
        const int k = (rowbase + c) + 512 * k1;
        const float2 xv = r1[sw(c * 512 + k1)];
        float2 v;
        if (PW == 1) {
            v = make_float2(0.f, 0.f);
            if (k < KK) {
                const float2 hv = Hc[(size_t)ch * M2 + k];
                const long long kk = (long long)k * k;
                const long long ra = (2LL * kk) % (2LL * NN1);
                const long long rb = kk % (2LL * NN2);
                const double ang = -(double)ra * (PI_D / (double)NN1)
                                   + (double)rb * (PI_D / (double)NN2);
                float sn, cs;
                sincosf((float)ang, &sn, &cs);
                float2 t = cmul(xv, hv);
                t = cmul(t, make_float2(cs, sn));
                constexpr float SC0 =
                    (float)(2.0 / ((double)NN2 * (double)M1 * (double)M2));
                const float sc = (k == 0 || k == KK - 1) ? 0.5f * SC0 : SC0;
                v = make_float2(t.x * sc, t.y * sc);
            }
        } else {
            v = cmul(xv, filt[k]);
        }
        other[sw(c * 512 + k1)] = v;
    }
    __syncthreads();
    constexpr bool D2 = (PW != 1);
    float2* r2 = block_fft8<512, 4, D2>(other, (other == sA) ? sB : sA, tw, tid);
    for (int i = tid; i < 2048; i += 256) {
        const int c = i & 3, k2p = i >> 2;
        const int col = rowbase + c;
        out[(size_t)k2p * 512 + col] =
            cmul(r2[sw(c * 512 + k2p)], wM<M1>((unsigned)(col * k2p), D2));
    }
}

// ---------------- fused M2 kernel: P2(fwd) + *B1fh + P1(inv) ----------------
__global__ void __launch_bounds__(256) k_fusedM2(const float2* __restrict__ in,
                                                 const float2* __restrict__ filt,
                                                 float2* __restrict__ out) {
    __shared__ float2 sA[2048], sB[2048], tw[512];
    const int tid = threadIdx.x;
    const int ch = blockIdx.y;
    in  += (size_t)ch * M2;
    out += (size_t)ch * M2;
    const int r = blockIdx.x * 2;
    for (int j = tid; j < 512; j += 256) tw[j] = g_T512[j];
    for (int i = tid; i < 1024; i += 256) {
        const int c = i >> 8, n1 = i & 255;
        const int row = r + (c & 1) + 256 * (c >> 1);
        sA[sw(c * 256 + n1)] = in[(size_t)row * 256 + n1];
    }
    __syncthreads();
    float2* r1 = block_fft8<256, 4, false>(sA, sB, tw, tid);
    float2* other = (r1 == sA) ? sB : sA;
    for (int i = tid; i < 1024; i += 256) {
        const int c0 = i & 1, n2 = i >> 1;
        const int k1 = n2 >> 1, hi = n2 & 1;
        const int k = (r + c0 + 256 * hi) + 512 * k1;
        other[sw(c0 * 512 + n2)] = cmul(r1[sw((2 * hi + c0) * 256 + k1)], filt[k]);
    }
    __syncthreads();
    float2* r2 = block_fft8<512, 2, true>(other, (other == sA) ? sB : sA, tw, tid);
    for (int i = tid; i < 1024; i += 256) {
        const int c0 = i & 1, k2p = i >> 1;
        const int col = r + c0;
        out[(size_t)k2p * 256 + col] =
            cmul(r2[sw(c0 * 512 + k2p)], wM<M2>((unsigned)(col * k2p), true));
    }
}

// ---------------- launcher ---------------------------------------------------
extern "C" void kernel_launch(void* const* d_in, const int* in_sizes, int n_in,
                              void* d_out, int out_size) {
    const float* x = (const float*)d_in[0];
    const float* h = (const float*)d_in[1];
    float* y = (float*)d_out;

    float2 *bufA, *bufB, *bufH, *FM1, *B1fh;
    cudaGetSymbolAddress((void**)&bufA, g_bufA);
    cudaGetSymbolAddress((void**)&bufB, g_bufB);
    cudaGetSymbolAddress((void**)&bufH, g_bufH);
    cudaGetSymbolAddress((void**)&FM1,  g_FM1);
    cudaGetSymbolAddress((void**)&B1fh, g_B1fh);
    float2* hs1 = bufA;
    float2* hs2 = bufA + (size_t)NCH * M2;

    k_tables<<<1, 512>>>();

    // filter spectra: B1f & Df batched (2 "channels"); B1fh separately
    k_pass1f<<<dim3(128, 2), 256>>>(bufB);
    k_pass2<M1, 512, false><<<dim3(128, 2), 256>>>(bufB, FM1);
    k_pass1g<M2, 256, 4><<<dim3(64, 1), 256>>>(nullptr, bufB);
    k_pass2<M2, 256, false><<<dim3(128, 1), 256>>>(bufB, B1fh);

    // h chain -> bufH
    k_pass1g<M2, 256, 1><<<dim3(64, NCH), 256>>>(h, hs1);
    k_fusedM2<<<dim3(128, NCH), 256>>>(hs1, B1fh, hs2);
    k_pass2<M2, 256, true><<<dim3(128, NCH), 256>>>(hs2, bufH);

    // x chain + combine + inverse chirp-Z + fused final
    k_pass1g<M1, 512, 0><<<dim3(128, NCH), 256>>>(x, bufB);
    k_fusedM1<0><<<dim3(128, NCH), 256>>>(bufB, FM1, nullptr, bufA);
    k_fusedM1<1><<<dim3(128, NCH), 256>>>(bufA, nullptr, bufH, bufB);
    k_fusedM1<2><<<dim3(128, NCH), 256>>>(bufB, FM1 + M1, nullptr, bufA);
    k_pass2f<<<dim3(128, NCH), 256>>>(bufA, y);
}

// round 11
// speedup vs baseline: 1.9443x; 1.0418x over previous
#include <cuda_runtime.h>
#include <math.h>

// y = irfft(rfft(x, n=139263) * rfft(h, n=139263))[..., :131072]
// rfft grid N1=139263 (odd), irfft default grid N2=139262.
// y[m] = (2/N2) Re sum_{k<K} c_k X_k H_k e^{2pi i k m/N2}, c_0=c_{K-1}=1/2.
// Bluestein chirp-Z on pow2 FFTs (M1=2^18 for x & inverse, M2=2^17 for h).
// v3.1: fully unrolled radix-8 Stockham (unity-twiddle tail), chirp tables,
// transposed H buffer, float4 global loads, 4-column fused M2 kernel.
// (resubmission of v3 after infra-class bench failure; audited, no code delta)

#define LX 131072
#define LH 8192
#define KK 69632
#define M1 262144
#define M2 131072
#define NCH 64
#define NN1 139263LL
#define NN2 139262LL
#define PI_D 3.14159265358979323846264338327950288

__device__ float2 g_bufA[(size_t)NCH * M1];
__device__ float2 g_bufB[(size_t)NCH * M1];
__device__ float2 g_bufH[(size_t)NCH * M2];   // TRANSPOSED: HT[k2*256+k1]
__device__ float2 g_FM1[2 * M1];   // [0]=B1f spectrum, [1]=Df spectrum (natural)
__device__ float2 g_B1fh[M2];      // natural
__device__ float2 g_CX[LX];        // e^{-i pi n^2/N1} (covers x and h prep)
__device__ float2 g_PC[KK];        // combine phase * scale
__device__ float2 g_CF[LX];        // e^{+i pi m^2/N2} / M1
__device__ float2 g_T512[512];
__device__ float2 g_TM1[512];
__device__ float2 g_TM2[512];

__device__ __forceinline__ float2 cmul(float2 a, float2 b) {
    return make_float2(a.x * b.x - a.y * b.y, a.x * b.y + a.y * b.x);
}
__device__ __forceinline__ float2 cadd(float2 a, float2 b) {
    return make_float2(a.x + b.x, a.y + b.y);
}
__device__ __forceinline__ float2 csub(float2 a, float2 b) {
    return make_float2(a.x - b.x, a.y - b.y);
}
__device__ __forceinline__ float2 chirp(long long u, long long nmod, float sgn) {
    const long long r = (u * u) % (2LL * nmod);
    const float ang = (float)((double)r * (PI_D / (double)nmod));
    float s, c;
    sincosf(ang, &s, &c);
    return make_float2(c, sgn * s);
}
// SMEM swizzle: XORs bits 4..7 into bits 0..3; bijective per 16-group; sw(e+1)=sw(e)^1 for even e.
__device__ __forceinline__ int sw(int i) { return i ^ ((i >> 4) & 15); }

__global__ void k_tables() {
    const int j = threadIdx.x;
    const double a = -2.0 * PI_D * (double)j;
    double s, c;
    sincos(a / 512.0, &s, &c);       g_T512[j] = make_float2((float)c, (float)s);
    sincos(a / (double)M1, &s, &c);  g_TM1[j]  = make_float2((float)c, (float)s);
    sincos(a / (double)M2, &s, &c);  g_TM2[j]  = make_float2((float)c, (float)s);
}

// Per-replay chirp/phase tables (channel-independent; L2-resident in hot passes)
__global__ void k_buildtabs() {
    const int i = blockIdx.x * 256 + threadIdx.x;   // < LX = 131072
    g_CX[i] = chirp(i, NN1, -1.f);
    {
        const float2 cf = chirp(i, NN2, 1.f);
        constexpr float INVM1 = 1.0f / (float)M1;
        g_CF[i] = make_float2(cf.x * INVM1, cf.y * INVM1);
    }
    if (i < KK) {
        const long long kk = (long long)i * i;
        const long long ra = (2LL * kk) % (2LL * NN1);
        const long long rb = kk % (2LL * NN2);
        const double ang = -(double)ra * (PI_D / (double)NN1)
                           + (double)rb * (PI_D / (double)NN2);
        float sn, cs;
        sincosf((float)ang, &sn, &cs);
        constexpr float SC0 = (float)(2.0 / ((double)NN2 * (double)M1 * (double)M2));
        const float sc = (i == 0 || i == KK - 1) ? 0.5f * SC0 : SC0;
        g_PC[i] = make_float2(cs * sc, sn * sc);
    }
}

// ---------------- register butterflies ---------------------------------------
template <bool INV>
__device__ __forceinline__ void dft4(float2& a, float2& b, float2& c, float2& d) {
    const float2 t0 = cadd(a, c), t1 = csub(a, c);
    const float2 t2 = cadd(b, d), t3 = csub(b, d);
    const float2 r = INV ? make_float2(-t3.y, t3.x) : make_float2(t3.y, -t3.x);
    a = cadd(t0, t2); b = cadd(t1, r); c = csub(t0, t2); d = csub(t1, r);
}
template <bool INV>
__device__ __forceinline__ void dft8(float2 v[8]) {
    float2 e0 = v[0], e1 = v[2], e2 = v[4], e3 = v[6];
    float2 o0 = v[1], o1 = v[3], o2 = v[5], o3 = v[7];
    dft4<INV>(e0, e1, e2, e3);
    dft4<INV>(o0, o1, o2, o3);
    const float r = 0.70710678118654752f;
    const float2 w1 = INV ? make_float2(r, r)  : make_float2(r, -r);
    const float2 w3 = INV ? make_float2(-r, r) : make_float2(-r, -r);
    o1 = cmul(o1, w1);
    o2 = INV ? make_float2(-o2.y, o2.x) : make_float2(o2.y, -o2.x);
    o3 = cmul(o3, w3);
    v[0] = cadd(e0, o0); v[4] = csub(e0, o0);
    v[1] = cadd(e1, o1); v[5] = csub(e1, o1);
    v[2] = cadd(e2, o2); v[6] = csub(e2, o2);
    v[3] = cadd(e3, o3); v[7] = csub(e3, o3);
}

// ---------------- unrolled Stockham stages -----------------------------------
// radix-8 stage: sub-size n=2^L2N, stride s=2^L2S. Final stage (L2N==3): p==0,
// unity twiddles (no loads, no cmuls).
template <bool INV, int L2S, int L2N, int LEN, int LPF>
__device__ __forceinline__ void st8(const float2* __restrict__ s, float2* __restrict__ d,
                                    const float2* __restrict__ tw, int go, int lane) {
    constexpr int NB = LEN / 8;
    constexpr int NIT = (NB + LPF - 1) / LPF;
#pragma unroll
    for (int it = 0; it < NIT; it++) {
        const int bf = it * LPF + lane;
        if (LPF > NB && bf >= NB) continue;
        const int p = bf >> L2S;
        const int q = bf & ((1 << L2S) - 1);
        float2 v[8];
#pragma unroll
        for (int m = 0; m < 8; m++) v[m] = s[go + sw(bf + m * NB)];
        dft8<INV>(v);
        const int ob = q + (p << (L2S + 3));
        d[go + sw(ob)] = v[0];
#pragma unroll
        for (int m = 1; m < 8; m++) {
            if (L2N == 3) {
                d[go + sw(ob + (m << L2S))] = v[m];
            } else {
                float2 w = tw[(p * m) << (9 - L2N)];
                if (INV) w.y = -w.y;
                d[go + sw(ob + (m << L2S))] = cmul(w, v[m]);
            }
        }
    }
}
// radix-4 tail (LEN=256 only): p==0, unity twiddles.
template <bool INV, int L2S, int LEN, int LPF>
__device__ __forceinline__ void st4(const float2* __restrict__ s, float2* __restrict__ d,
                                    int go, int lane) {
    constexpr int NB = LEN / 4;
    constexpr int NIT = (NB + LPF - 1) / LPF;
#pragma unroll
    for (int it = 0; it < NIT; it++) {
        const int bf = it * LPF + lane;
        if (LPF > NB && bf >= NB) continue;
        float2 a = s[go + sw(bf)];
        float2 b = s[go + sw(bf + NB)];
        float2 c = s[go + sw(bf + 2 * NB)];
        float2 e = s[go + sw(bf + 3 * NB)];
        dft4<INV>(a, b, c, e);
        d[go + sw(bf)] = a;
        d[go + sw(bf + (1 << L2S))] = b;
        d[go + sw(bf + (2 << L2S))] = c;
        d[go + sw(bf + (3 << L2S))] = e;
    }
}

// NFFT transforms of length LEN; 256 threads; result ALWAYS in B.
template <int LEN, int NFFT, bool INV>
__device__ __forceinline__ float2* block_fft8(float2* A, float2* B, const float2* tw, int tid) {
    constexpr int LPF = 256 / NFFT;
    const int g = tid / LPF, lane = tid % LPF;
    const int go = g * LEN;
    if constexpr (LEN == 512) {
        st8<INV, 0, 9, 512, LPF>(A, B, tw, go, lane); __syncthreads();
        st8<INV, 3, 6, 512, LPF>(B, A, tw, go, lane); __syncthreads();
        st8<INV, 6, 3, 512, LPF>(A, B, tw, go, lane); __syncthreads();
    } else {
        st8<INV, 0, 8, 256, LPF>(A, B, tw, go, lane); __syncthreads();
        st8<INV, 3, 5, 256, LPF>(B, A, tw, go, lane); __syncthreads();
        st4<INV, 6, 256, LPF>(A, B, go, lane); __syncthreads();
    }
    return B;
}

template <int MSZ>
__device__ __forceinline__ float2 wM(unsigned a, bool conj) {
    constexpr int HS = (512 * 512) / MSZ;
    const float2* lo = (MSZ == M1) ? g_TM1 : g_TM2;
    float2 w = cmul(g_T512[(a >> 9) * HS], lo[a & 511]);
    if (conj) w.y = -w.y;
    return w;
}

// ---------------- pass1 with generated input --------------------------------
// MODE: 0=load_x (M1), 1=load_h (M2), 4=gen_B1h (M2)
template <int MSZ, int NA, int MODE>
__global__ void __launch_bounds__(256) k_pass1g(const float* __restrict__ src,
                                                float2* __restrict__ out) {
    __shared__ float2 sA[2048], sB[2048], tw[512];
    const int tid = threadIdx.x;
    const int ch = blockIdx.y;
    out += (size_t)ch * MSZ;
    const int colbase = blockIdx.x * 4;
    for (int j = tid; j < 512; j += 256) tw[j] = g_T512[j];
    for (int i = tid; i < 4 * 512; i += 256) {
        const int c = i & 3, t = i >> 2;
        const int n = (colbase + c) + NA * t;
        float2 v = make_float2(0.f, 0.f);
        if (MODE == 0) {
            if (n < LX) {
                const float xv = src[(size_t)ch * LX + n];
                const float2 cc = g_CX[n];
                v = make_float2(xv * cc.x, xv * cc.y);
            }
        } else if (MODE == 1) {
            if (n < LH) {
                const float hv = src[(size_t)ch * LH + n];
                const float2 cc = g_CX[n];
                v = make_float2(hv * cc.x, hv * cc.y);
            }
        } else {
            if (n < KK)                 v = chirp(n, NN1, 1.f);
            else if (n >= M2 - LH + 1)  v = chirp((long long)(M2 - n), NN1, 1.f);
        }
        sA[sw(c * 512 + t)] = v;
    }
    __syncthreads();
    float2* res = block_fft8<512, 4, false>(sA, sB, tw, tid);
    for (int i = tid; i < 4 * 512; i += 256) {
        const int c = i & 3, k2 = i >> 2;
        const int col = colbase + c;
        out[(size_t)k2 * NA + col] =
            cmul(res[sw(c * 512 + k2)], wM<MSZ>((unsigned)(col * k2), false));
    }
}

// filter generator pass1 (M1): blockIdx.y: 0 -> chirp b (N1), 1 -> chirp d (N2)
__global__ void __launch_bounds__(256) k_pass1f(float2* __restrict__ out) {
    __shared__ float2 sA[2048], sB[2048], tw[512];
    const int tid = threadIdx.x;
    const int which = blockIdx.y;
    out += (size_t)which * M1;
    const int colbase = blockIdx.x * 4;
    for (int j = tid; j < 512; j += 256) tw[j] = g_T512[j];
    for (int i = tid; i < 4 * 512; i += 256) {
        const int c = i & 3, t = i >> 2;
        const int n = (colbase + c) + 512 * t;
        float2 v = make_float2(0.f, 0.f);
        if (which == 0) {
            if (n < KK)                 v = chirp(n, NN1, 1.f);
            else if (n >= M1 - LX + 1)  v = chirp((long long)(M1 - n), NN1, 1.f);
        } else {
            if (n < LX)                 v = chirp(n, NN2, -1.f);
            else if (n >= M1 - KK + 1)  v = chirp((long long)(M1 - n), NN2, -1.f);
        }
        sA[sw(c * 512 + t)] = v;
    }
    __syncthreads();
    float2* res = block_fft8<512, 4, false>(sA, sB, tw, tid);
    for (int i = tid; i < 4 * 512; i += 256) {
        const int c = i & 3, k2 = i >> 2;
        const int col = colbase + c;
        out[(size_t)k2 * 512 + col] =
            cmul(res[sw(c * 512 + k2)], wM<M1>((unsigned)(col * k2), false));
    }
}

// ---------------- plain pass2 (precompute; natural-order output) -------------
template <int MSZ, int NA, bool INV>
__global__ void __launch_bounds__(256) k_pass2(const float2* __restrict__ in,
                                               float2* __restrict__ out) {
    __shared__ float2 sA[2048], sB[2048], tw[512];
    const int tid = threadIdx.x;
    in  += (size_t)blockIdx.y * MSZ;
    out += (size_t)blockIdx.y * MSZ;
    const int rowbase = blockIdx.x * 4;
    for (int j = tid; j < 512; j += 256) tw[j] = g_T512[j];
    for (int i = tid; i < 4 * NA; i += 256) {
        const int c = i / NA, n1 = i % NA;
        sA[sw(c * NA + n1)] = in[(size_t)(rowbase + c) * NA + n1];
    }
    __syncthreads();
    float2* res = block_fft8<NA, 4, INV>(sA, sB, tw, tid);
    constexpr int NROW = MSZ / NA;
    for (int i = tid; i < 4 * NA; i += 256) {
        const int c = i & 3, k1 = i >> 2;
        out[(size_t)(rowbase + c) + NROW * k1] = res[sw(c * NA + k1)];
    }
}

// pass2 (M2, inverse), TRANSPOSED output HT[k2*256+k1] (contiguous writes) ----
__global__ void __launch_bounds__(256) k_pass2t(const float2* __restrict__ in,
                                                float2* __restrict__ out) {
    __shared__ float2 sA[2048], sB[2048], tw[512];
    const int tid = threadIdx.x;
    in  += (size_t)blockIdx.y * M2;
    out += (size_t)blockIdx.y * M2;
    const int rowbase = blockIdx.x * 4;
    for (int j = tid; j < 512; j += 256) tw[j] = g_T512[j];
    const float4* in4 = reinterpret_cast<const float4*>(in) + (size_t)rowbase * 128;
    for (int i = tid; i < 512; i += 256) {
        const int c = i >> 7, j = i & 127;
        const float4 w4 = in4[c * 128 + j];
        const int s0 = sw(c * 256 + 2 * j);
        sA[s0] = make_float2(w4.x, w4.y);
        sA[s0 ^ 1] = make_float2(w4.z, w4.w);
    }
    __syncthreads();
    float2* res = block_fft8<256, 4, true>(sA, sB, tw, tid);
    float4* out4 = reinterpret_cast<float4*>(out) + (size_t)rowbase * 128;
    for (int i = tid; i < 512; i += 256) {
        const int c = i >> 7, j = i & 127;
        const int s0 = sw(c * 256 + 2 * j);
        const float2 lo = res[s0], hi = res[s0 ^ 1];
        out4[c * 128 + j] = make_float4(lo.x, lo.y, hi.x, hi.y);
    }
}

// pass2 (M1, inverse) fused with final chirp + real output (uses g_CF) -------
__global__ void __launch_bounds__(256) k_pass2f(const float2* __restrict__ in,
                                                float* __restrict__ y) {
    __shared__ float2 sA[2048], sB[2048], tw[512];
    const int tid = threadIdx.x;
    const int ch = blockIdx.y;
    in += (size_t)ch * M1;
    const int rowbase = blockIdx.x * 4;
    for (int j = tid; j < 512; j += 256) tw[j] = g_T512[j];
    const float4* in4 = reinterpret_cast<const float4*>(in) + (size_t)rowbase * 256;
    for (int i = tid; i < 1024; i += 256) {
        const int c = i >> 8, j = i & 255;
        const float4 w4 = in4[c * 256 + j];
        const int s0 = sw(c * 512 + 2 * j);
        sA[s0] = make_float2(w4.x, w4.y);
        sA[s0 ^ 1] = make_float2(w4.z, w4.w);
    }
    __syncthreads();
    float2* res = block_fft8<512, 4, true>(sA, sB, tw, tid);
    for (int i = tid; i < 2048; i += 256) {
        const int c = i & 3, k1 = i >> 2;
        const int m = (rowbase + c) + 512 * k1;
        if (m < LX) {
            const float2 sv = res[sw(c * 512 + k1)];
            const float2 cf = g_CF[m];               // includes 1/M1
            y[(size_t)ch * LX + m] = sv.x * cf.x - sv.y * cf.y;
        }
    }
}

// ---------------- fused M1 kernel: P2(dir1) + pointwise + P1(dir2) ----------
// PW=0: fwd, *B1f, inv | PW=1: inv, combine(HT,PC), fwd | PW=2: fwd, *Df, inv
template <int PW>
__global__ void __launch_bounds__(256) k_fusedM1(const float2* __restrict__ in,
                                                 const float2* __restrict__ filt,
                                                 const float2* __restrict__ Hc,
                                                 float2* __restrict__ out) {
    __shared__ float2 sA[2048], sB[2048], tw[512];
    const int tid = threadIdx.x;
    const int ch = blockIdx.y;
    in  += (size_t)ch * M1;
    out += (size_t)ch * M1;
    const int rowbase = blockIdx.x * 4;
    for (int j = tid; j < 512; j += 256) tw[j] = g_T512[j];
    const float4* in4 = reinterpret_cast<const float4*>(in) + (size_t)rowbase * 256;
    for (int i = tid; i < 1024; i += 256) {
        const int c = i >> 8, j = i & 255;
        const float4 w4 = in4[c * 256 + j];
        const int s0 = sw(c * 512 + 2 * j);
        sA[s0] = make_float2(w4.x, w4.y);
        sA[s0 ^ 1] = make_float2(w4.z, w4.w);
    }
    __syncthreads();
    constexpr bool D1 = (PW == 1);
    float2* r1 = block_fft8<512, 4, D1>(sA, sB, tw, tid);   // == sB
    for (int i = tid; i < 2048; i += 256) {
        const int c = i & 3, k1 = i >> 2;
        const int k = (rowbase + c) + 512 * k1;
        const float2 xv = r1[sw(c * 512 + k1)];
        float2 v;
        if (PW == 1) {
            v = make_float2(0.f, 0.f);
            if (k < KK) {
                // transposed H: HT[k2*256 + k1]; k<KK => k1 <= 135 < 256
                const float2 hv = Hc[(size_t)ch * M2 + (size_t)(rowbase + c) * 256 + k1];
                v = cmul(cmul(xv, hv), g_PC[k]);
            }
        } else {
            v = cmul(xv, filt[k]);
        }
        sA[sw(c * 512 + k1)] = v;
    }
    __syncthreads();
    constexpr bool D2 = (PW != 1);
    float2* r2 = block_fft8<512, 4, D2>(sA, sB, tw, tid);   // == sB
    for (int i = tid; i < 2048; i += 256) {
        const int c = i & 3, k2p = i >> 2;
        const int col = rowbase + c;
        out[(size_t)k2p * 512 + col] =
            cmul(r2[sw(c * 512 + k2p)], wM<M1>((unsigned)(col * k2p), D2));
    }
}

// ---------------- fused M2 kernel: P2(fwd) + *B1fh + P1(inv), 4 columns -----
// Block owns rows {r+c0+256*hi : c0<4, hi<2} (r=4*bx) == P1inv columns r..r+3.
__global__ void __launch_bounds__(256) k_fusedM2(const float2* __restrict__ in,
                                                 const float2* __restrict__ filt,
                                                 float2* __restrict__ out) {
    __shared__ float2 sA[2048], sB[2048], tw[512];
    const int tid = threadIdx.x;
    const int ch = blockIdx.y;
    in  += (size_t)ch * M2;
    out += (size_t)ch * M2;
    const int r = blockIdx.x * 4;
    for (int j = tid; j < 512; j += 256) tw[j] = g_T512[j];
    for (int i = tid; i < 1024; i += 256) {
        const int c = i >> 7, j = i & 127;                  // c<8 rows, j<128 float4
        const int row = r + (c & 3) + 256 * (c >> 2);
        const float4 w4 = reinterpret_cast<const float4*>(in)[(size_t)row * 128 + j];
        const int s0 = sw(c * 256 + 2 * j);
        sA[s0] = make_float2(w4.x, w4.y);
        sA[s0 ^ 1] = make_float2(w4.z, w4.w);
    }
    __syncthreads();
    float2* r1 = block_fft8<256, 8, false>(sA, sB, tw, tid);  // == sB
    // reorg + filter: S[c0*512 + n2] = r1[(c0+4*hi)*256 + k1] * filt[k],
    // n2 = 2*k1 + hi, k = (r + c0 + 256*hi) + 512*k1
    for (int i = tid; i < 2048; i += 256) {
        const int c0 = i & 3, n2 = i >> 2;
        const int k1 = n2 >> 1, hi = n2 & 1;
        const int k = (r + c0 + 256 * hi) + 512 * k1;
        sA[sw(c0 * 512 + n2)] = cmul(r1[sw((c0 + 4 * hi) * 256 + k1)], filt[k]);
    }
    __syncthreads();
    float2* r2 = block_fft8<512, 4, true>(sA, sB, tw, tid);   // == sB
    for (int i = tid; i < 2048; i += 256) {
        const int c0 = i & 3, k2p = i >> 2;
        const int col = r + c0;
        out[(size_t)k2p * 256 + col] =
            cmul(r2[sw(c0 * 512 + k2p)], wM<M2>((unsigned)(col * k2p), true));
    }
}

// ---------------- launcher ---------------------------------------------------
extern "C" void kernel_launch(void* const* d_in, const int* in_sizes, int n_in,
                              void* d_out, int out_size) {
    const float* x = (const float*)d_in[0];
    const float* h = (const float*)d_in[1];
    float* y = (float*)d_out;

    float2 *bufA, *bufB, *bufH, *FM1, *B1fh;
    cudaGetSymbolAddress((void**)&bufA, g_bufA);
    cudaGetSymbolAddress((void**)&bufB, g_bufB);
    cudaGetSymbolAddress((void**)&bufH, g_bufH);
    cudaGetSymbolAddress((void**)&FM1,  g_FM1);
    cudaGetSymbolAddress((void**)&B1fh, g_B1fh);
    float2* hs1 = bufA;
    float2* hs2 = bufA + (size_t)NCH * M2;

    k_tables<<<1, 512>>>();
    k_buildtabs<<<LX / 256, 256>>>();

    // filter spectra: B1f & Df batched; B1fh separately (natural layouts)
    k_pass1f<<<dim3(128, 2), 256>>>(bufB);
    k_pass2<M1, 512, false><<<dim3(128, 2), 256>>>(bufB, FM1);
    k_pass1g<M2, 256, 4><<<dim3(64, 1), 256>>>(nullptr, bufB);
    k_pass2<M2, 256, false><<<dim3(128, 1), 256>>>(bufB, B1fh);

    // h chain -> bufH (transposed HT[k2*256+k1])
    k_pass1g<M2, 256, 1><<<dim3(64, NCH), 256>>>(h, hs1);
    k_fusedM2<<<dim3(64, NCH), 256>>>(hs1, B1fh, hs2);
    k_pass2t<<<dim3(128, NCH), 256>>>(hs2, bufH);

    // x chain + combine + inverse chirp-Z + fused final
    k_pass1g<M1, 512, 0><<<dim3(128, NCH), 256>>>(x, bufB);
    k_fusedM1<0><<<dim3(128, NCH), 256>>>(bufB, FM1, nullptr, bufA);
    k_fusedM1<1><<<dim3(128, NCH), 256>>>(bufA, nullptr, bufH, bufB);
    k_fusedM1<2><<<dim3(128, NCH), 256>>>(bufB, FM1 + M1, nullptr, bufA);
    k_pass2f<<<dim3(128, NCH), 256>>>(bufA, y);
}

// round 12
// speedup vs baseline: 1.9818x; 1.0193x over previous
#include <cuda_runtime.h>
#include <math.h>

// y = irfft(rfft(x, n=139263) * rfft(h, n=139263))[..., :131072]
// rfft grid N1=139263 (odd), irfft default grid N2=139262.
// y[m] = (2/N2) Re sum_{k<K} c_k X_k H_k e^{2pi i k m/N2}, c_0=c_{K-1}=1/2.
// Bluestein chirp-Z on pow2 FFTs (M1=2^18 for x & inverse, M2=2^17 for h).
// v4: launch-merged pipeline (7 launches). Independent passes share launches
// via block-range dispatch; the h-chain's final pass2 is fused into the
// combine kernel (1:1 block correspondence), removing the HT global buffer.

#define LX 131072
#define LH 8192
#define KK 69632
#define M1 262144
#define M2 131072
#define NCH 64
#define NN1 139263LL
#define NN2 139262LL
#define PI_D 3.14159265358979323846264338327950288

__device__ float2 g_bufA[(size_t)NCH * M1];
__device__ float2 g_bufB[(size_t)NCH * M1];
__device__ float2 g_bufC[(size_t)NCH * M1];   // hs1 | hs2 (each NCH*M2)
__device__ float2 g_FM1[2 * M1];   // [0]=B1f spectrum, [1]=Df spectrum
__device__ float2 g_B1fh[M2];
__device__ float2 g_CX[LX];        // e^{-i pi n^2/N1}
__device__ float2 g_PC[KK];        // combine phase * scale
__device__ float2 g_CF[LX];        // e^{+i pi m^2/N2} / M1
__device__ float2 g_T512[512];
__device__ float2 g_TM1[512];
__device__ float2 g_TM2[512];

__device__ __forceinline__ float2 cmul(float2 a, float2 b) {
    return make_float2(a.x * b.x - a.y * b.y, a.x * b.y + a.y * b.x);
}
__device__ __forceinline__ float2 cadd(float2 a, float2 b) {
    return make_float2(a.x + b.x, a.y + b.y);
}
__device__ __forceinline__ float2 csub(float2 a, float2 b) {
    return make_float2(a.x - b.x, a.y - b.y);
}
__device__ __forceinline__ float2 chirp(long long u, long long nmod, float sgn) {
    const long long r = (u * u) % (2LL * nmod);
    const float ang = (float)((double)r * (PI_D / (double)nmod));
    float s, c;
    sincosf(ang, &s, &c);
    return make_float2(c, sgn * s);
}
__device__ __forceinline__ int sw(int i) { return i ^ ((i >> 4) & 15); }

// ---------------- register butterflies ---------------------------------------
template <bool INV>
__device__ __forceinline__ void dft4(float2& a, float2& b, float2& c, float2& d) {
    const float2 t0 = cadd(a, c), t1 = csub(a, c);
    const float2 t2 = cadd(b, d), t3 = csub(b, d);
    const float2 r = INV ? make_float2(-t3.y, t3.x) : make_float2(t3.y, -t3.x);
    a = cadd(t0, t2); b = cadd(t1, r); c = csub(t0, t2); d = csub(t1, r);
}
template <bool INV>
__device__ __forceinline__ void dft8(float2 v[8]) {
    float2 e0 = v[0], e1 = v[2], e2 = v[4], e3 = v[6];
    float2 o0 = v[1], o1 = v[3], o2 = v[5], o3 = v[7];
    dft4<INV>(e0, e1, e2, e3);
    dft4<INV>(o0, o1, o2, o3);
    const float r = 0.70710678118654752f;
    const float2 w1 = INV ? make_float2(r, r)  : make_float2(r, -r);
    const float2 w3 = INV ? make_float2(-r, r) : make_float2(-r, -r);
    o1 = cmul(o1, w1);
    o2 = INV ? make_float2(-o2.y, o2.x) : make_float2(o2.y, -o2.x);
    o3 = cmul(o3, w3);
    v[0] = cadd(e0, o0); v[4] = csub(e0, o0);
    v[1] = cadd(e1, o1); v[5] = csub(e1, o1);
    v[2] = cadd(e2, o2); v[6] = csub(e2, o2);
    v[3] = cadd(e3, o3); v[7] = csub(e3, o3);
}

// ---------------- unrolled Stockham stages -----------------------------------
template <bool INV, int L2S, int L2N, int LEN, int LPF>
__device__ __forceinline__ void st8(const float2* __restrict__ s, float2* __restrict__ d,
                                    const float2* __restrict__ tw, int go, int lane) {
    constexpr int NB = LEN / 8;
    constexpr int NIT = (NB + LPF - 1) / LPF;
#pragma unroll
    for (int it = 0; it < NIT; it++) {
        const int bf = it * LPF + lane;
        if (LPF > NB && bf >= NB) continue;
        const int p = bf >> L2S;
        const int q = bf & ((1 << L2S) - 1);
        float2 v[8];
#pragma unroll
        for (int m = 0; m < 8; m++) v[m] = s[go + sw(bf + m * NB)];
        dft8<INV>(v);
        const int ob = q + (p << (L2S + 3));
        d[go + sw(ob)] = v[0];
#pragma unroll
        for (int m = 1; m < 8; m++) {
            if (L2N == 3) {
                d[go + sw(ob + (m << L2S))] = v[m];
            } else {
                float2 w = tw[(p * m) << (9 - L2N)];
                if (INV) w.y = -w.y;
                d[go + sw(ob + (m << L2S))] = cmul(w, v[m]);
            }
        }
    }
}
template <bool INV, int L2S, int LEN, int LPF>
__device__ __forceinline__ void st4(const float2* __restrict__ s, float2* __restrict__ d,
                                    int go, int lane) {
    constexpr int NB = LEN / 4;
    constexpr int NIT = (NB + LPF - 1) / LPF;
#pragma unroll
    for (int it = 0; it < NIT; it++) {
        const int bf = it * LPF + lane;
        if (LPF > NB && bf >= NB) continue;
        float2 a = s[go + sw(bf)];
        float2 b = s[go + sw(bf + NB)];
        float2 c = s[go + sw(bf + 2 * NB)];
        float2 e = s[go + sw(bf + 3 * NB)];
        dft4<INV>(a, b, c, e);
        d[go + sw(bf)] = a;
        d[go + sw(bf + (1 << L2S))] = b;
        d[go + sw(bf + (2 << L2S))] = c;
        d[go + sw(bf + (3 << L2S))] = e;
    }
}

// NFFT transforms of length LEN; 256 threads; result ALWAYS in B.
template <int LEN, int NFFT, bool INV>
__device__ __forceinline__ float2* block_fft8(float2* A, float2* B, const float2* tw, int tid) {
    constexpr int LPF = 256 / NFFT;
    const int g = tid / LPF, lane = tid % LPF;
    const int go = g * LEN;
    if constexpr (LEN == 512) {
        st8<INV, 0, 9, 512, LPF>(A, B, tw, go, lane); __syncthreads();
        st8<INV, 3, 6, 512, LPF>(B, A, tw, go, lane); __syncthreads();
        st8<INV, 6, 3, 512, LPF>(A, B, tw, go, lane); __syncthreads();
    } else {
        st8<INV, 0, 8, 256, LPF>(A, B, tw, go, lane); __syncthreads();
        st8<INV, 3, 5, 256, LPF>(B, A, tw, go, lane); __syncthreads();
        st4<INV, 6, 256, LPF>(A, B, go, lane); __syncthreads();
    }
    return B;
}

template <int MSZ>
__device__ __forceinline__ float2 wM(unsigned a, bool conj) {
    constexpr int HS = (512 * 512) / MSZ;
    const float2* lo = (MSZ == M1) ? g_TM1 : g_TM2;
    float2 w = cmul(g_T512[(a >> 9) * HS], lo[a & 511]);
    if (conj) w.y = -w.y;
    return w;
}

__device__ __forceinline__ void load_tw(float2* tw, int tid) {
    for (int j = tid; j < 512; j += 256) tw[j] = g_T512[j];
}

// ================= device pass bodies =========================================

// pass1 with generated input. MODE: 0=x(M1), 1=h(M2), 4=B1h chirp(M2)
template <int MSZ, int NA, int MODE>
__device__ void dev_p1g(const float* __restrict__ src, float2* __restrict__ out,
                        int bx, int ch, float2* sA, float2* sB, float2* tw, int tid) {
    out += (size_t)ch * MSZ;
    const int colbase = bx * 4;
    load_tw(tw, tid);
    for (int i = tid; i < 4 * 512; i += 256) {
        const int c = i & 3, t = i >> 2;
        const int n = (colbase + c) + NA * t;
        float2 v = make_float2(0.f, 0.f);
        if (MODE == 0) {
            if (n < LX) {
                const float xv = src[(size_t)ch * LX + n];
                const float2 cc = g_CX[n];
                v = make_float2(xv * cc.x, xv * cc.y);
            }
        } else if (MODE == 1) {
            if (n < LH) {
                const float hv = src[(size_t)ch * LH + n];
                const float2 cc = g_CX[n];
                v = make_float2(hv * cc.x, hv * cc.y);
            }
        } else {
            if (n < KK)                 v = chirp(n, NN1, 1.f);
            else if (n >= M2 - LH + 1)  v = chirp((long long)(M2 - n), NN1, 1.f);
        }
        sA[sw(c * 512 + t)] = v;
    }
    __syncthreads();
    float2* res = block_fft8<512, 4, false>(sA, sB, tw, tid);
    for (int i = tid; i < 4 * 512; i += 256) {
        const int c = i & 3, k2 = i >> 2;
        const int col = colbase + c;
        out[(size_t)k2 * NA + col] =
            cmul(res[sw(c * 512 + k2)], wM<MSZ>((unsigned)(col * k2), false));
    }
}

// filter generator pass1 (M1): which: 0 -> chirp b (N1), 1 -> chirp d (N2)
__device__ void dev_p1f(float2* __restrict__ out, int bx, int which,
                        float2* sA, float2* sB, float2* tw, int tid) {
    out += (size_t)which * M1;
    const int colbase = bx * 4;
    load_tw(tw, tid);
    for (int i = tid; i < 4 * 512; i += 256) {
        const int c = i & 3, t = i >> 2;
        const int n = (colbase + c) + 512 * t;
        float2 v = make_float2(0.f, 0.f);
        if (which == 0) {
            if (n < KK)                 v = chirp(n, NN1, 1.f);
            else if (n >= M1 - LX + 1)  v = chirp((long long)(M1 - n), NN1, 1.f);
        } else {
            if (n < LX)                 v = chirp(n, NN2, -1.f);
            else if (n >= M1 - KK + 1)  v = chirp((long long)(M1 - n), NN2, -1.f);
        }
        sA[sw(c * 512 + t)] = v;
    }
    __syncthreads();
    float2* res = block_fft8<512, 4, false>(sA, sB, tw, tid);
    for (int i = tid; i < 4 * 512; i += 256) {
        const int c = i & 3, k2 = i >> 2;
        const int col = colbase + c;
        out[(size_t)k2 * 512 + col] =
            cmul(res[sw(c * 512 + k2)], wM<M1>((unsigned)(col * k2), false));
    }
}

// plain pass2 (natural-order output)
template <int MSZ, int NA, bool INV>
__device__ void dev_p2(const float2* __restrict__ in, float2* __restrict__ out,
                       int bx, float2* sA, float2* sB, float2* tw, int tid) {
    const int rowbase = bx * 4;
    load_tw(tw, tid);
    for (int i = tid; i < 4 * NA; i += 256) {
        const int c = i / NA, n1 = i % NA;
        sA[sw(c * NA + n1)] = in[(size_t)(rowbase + c) * NA + n1];
    }
    __syncthreads();
    float2* res = block_fft8<NA, 4, INV>(sA, sB, tw, tid);
    constexpr int NROW = MSZ / NA;
    for (int i = tid; i < 4 * NA; i += 256) {
        const int c = i & 3, k1 = i >> 2;
        out[(size_t)(rowbase + c) + NROW * k1] = res[sw(c * NA + k1)];
    }
}

// fused M1: P2(dir1) + pointwise (*filt) + P1(dir2).  PW=0: fwd/B1f/inv, PW=2: fwd/Df/inv
template <int PW>
__device__ void dev_fusedM1(const float2* __restrict__ in, const float2* __restrict__ filt,
                            float2* __restrict__ out, int bx, int ch,
                            float2* sA, float2* sB, float2* tw, int tid) {
    in  += (size_t)ch * M1;
    out += (size_t)ch * M1;
    const int rowbase = bx * 4;
    load_tw(tw, tid);
    const float4* in4 = reinterpret_cast<const float4*>(in) + (size_t)rowbase * 256;
    for (int i = tid; i < 1024; i += 256) {
        const int c = i >> 8, j = i & 255;
        const float4 w4 = in4[c * 256 + j];
        const int s0 = sw(c * 512 + 2 * j);
        sA[s0] = make_float2(w4.x, w4.y);
        sA[s0 ^ 1] = make_float2(w4.z, w4.w);
    }
    __syncthreads();
    float2* r1 = block_fft8<512, 4, false>(sA, sB, tw, tid);
    for (int i = tid; i < 2048; i += 256) {
        const int c = i & 3, k1 = i >> 2;
        const int k = (rowbase + c) + 512 * k1;
        sA[sw(c * 512 + k1)] = cmul(r1[sw(c * 512 + k1)], filt[k]);
    }
    __syncthreads();
    float2* r2 = block_fft8<512, 4, true>(sA, sB, tw, tid);
    for (int i = tid; i < 2048; i += 256) {
        const int c = i & 3, k2p = i >> 2;
        const int col = rowbase + c;
        out[(size_t)k2p * 512 + col] =
            cmul(r2[sw(c * 512 + k2p)], wM<M1>((unsigned)(col * k2p), true));
    }
}

// fused combine (PW=1 of old fusedM1) with h-chain pass2 prefused:
// step A: inverse FFT-256 of hs2 rows (rowbase..+3) -> H values kept in sH.
// step B: P2(inv) of x-conv + combine(sH, g_PC) + P1(fwd).
__device__ void dev_fusedComb(const float2* __restrict__ in, const float2* __restrict__ hs2,
                              float2* __restrict__ out, int bx, int ch,
                              float2* sA, float2* sB, float2* tw, float2* sH, int tid) {
    in  += (size_t)ch * M1;
    out += (size_t)ch * M1;
    hs2 += (size_t)ch * M2;
    const int rowbase = bx * 4;
    load_tw(tw, tid);
    // --- step A: H rows ---
    for (int i = tid; i < 1024; i += 256) {
        const int c = i >> 8, n1 = i & 255;
        sA[sw(c * 256 + n1)] = hs2[(size_t)(rowbase + c) * 256 + n1];
    }
    __syncthreads();
    {
        float2* resH = block_fft8<256, 4, true>(sA, sB, tw, tid);
        // k = (rowbase+c) + 512*k1 < KK=512*136  <=>  k1 < 136
        for (int i = tid; i < 4 * 136; i += 256) {
            const int c = i / 136, k1 = i % 136;
            sH[c * 136 + k1] = resH[sw(c * 256 + k1)];
        }
    }
    __syncthreads();
    // --- step B: main flow ---
    const float4* in4 = reinterpret_cast<const float4*>(in) + (size_t)rowbase * 256;
    for (int i = tid; i < 1024; i += 256) {
        const int c = i >> 8, j = i & 255;
        const float4 w4 = in4[c * 256 + j];
        const int s0 = sw(c * 512 + 2 * j);
        sA[s0] = make_float2(w4.x, w4.y);
        sA[s0 ^ 1] = make_float2(w4.z, w4.w);
    }
    __syncthreads();
    float2* r1 = block_fft8<512, 4, true>(sA, sB, tw, tid);
    for (int i = tid; i < 2048; i += 256) {
        const int c = i & 3, k1 = i >> 2;
        const int k = (rowbase + c) + 512 * k1;
        const float2 xv = r1[sw(c * 512 + k1)];
        float2 v = make_float2(0.f, 0.f);
        if (k1 < 136) {            // k < KK exactly
            v = cmul(cmul(xv, sH[c * 136 + k1]), g_PC[k]);
        }
        sA[sw(c * 512 + k1)] = v;
    }
    __syncthreads();
    float2* r2 = block_fft8<512, 4, false>(sA, sB, tw, tid);
    for (int i = tid; i < 2048; i += 256) {
        const int c = i & 3, k2p = i >> 2;
        const int col = rowbase + c;
        out[(size_t)k2p * 512 + col] =
            cmul(r2[sw(c * 512 + k2p)], wM<M1>((unsigned)(col * k2p), false));
    }
}

// fused M2: P2(fwd) + *B1fh + P1(inv), 4 columns per block
__device__ void dev_fusedM2(const float2* __restrict__ in, const float2* __restrict__ filt,
                            float2* __restrict__ out, int bx, int ch,
                            float2* sA, float2* sB, float2* tw, int tid) {
    in  += (size_t)ch * M2;
    out += (size_t)ch * M2;
    const int r = bx * 4;
    load_tw(tw, tid);
    for (int i = tid; i < 1024; i += 256) {
        const int c = i >> 7, j = i & 127;
        const int row = r + (c & 3) + 256 * (c >> 2);
        const float4 w4 = reinterpret_cast<const float4*>(in)[(size_t)row * 128 + j];
        const int s0 = sw(c * 256 + 2 * j);
        sA[s0] = make_float2(w4.x, w4.y);
        sA[s0 ^ 1] = make_float2(w4.z, w4.w);
    }
    __syncthreads();
    float2* r1 = block_fft8<256, 8, false>(sA, sB, tw, tid);
    for (int i = tid; i < 2048; i += 256) {
        const int c0 = i & 3, n2 = i >> 2;
        const int k1 = n2 >> 1, hi = n2 & 1;
        const int k = (r + c0 + 256 * hi) + 512 * k1;
        sA[sw(c0 * 512 + n2)] = cmul(r1[sw((c0 + 4 * hi) * 256 + k1)], filt[k]);
    }
    __syncthreads();
    float2* r2 = block_fft8<512, 4, true>(sA, sB, tw, tid);
    for (int i = tid; i < 2048; i += 256) {
        const int c0 = i & 3, k2p = i >> 2;
        const int col = r + c0;
        out[(size_t)k2p * 256 + col] =
            cmul(r2[sw(c0 * 512 + k2p)], wM<M2>((unsigned)(col * k2p), true));
    }
}

// pass2 (M1, inverse) fused with final chirp + real output
__device__ void dev_p2f(const float2* __restrict__ in, float* __restrict__ y,
                        int bx, int ch, float2* sA, float2* sB, float2* tw, int tid) {
    in += (size_t)ch * M1;
    const int rowbase = bx * 4;
    load_tw(tw, tid);
    const float4* in4 = reinterpret_cast<const float4*>(in) + (size_t)rowbase * 256;
    for (int i = tid; i < 1024; i += 256) {
        const int c = i >> 8, j = i & 255;
        const float4 w4 = in4[c * 256 + j];
        const int s0 = sw(c * 512 + 2 * j);
        sA[s0] = make_float2(w4.x, w4.y);
        sA[s0 ^ 1] = make_float2(w4.z, w4.w);
    }
    __syncthreads();
    float2* res = block_fft8<512, 4, true>(sA, sB, tw, tid);
    for (int i = tid; i < 2048; i += 256) {
        const int c = i & 3, k1 = i >> 2;
        const int m = (rowbase + c) + 512 * k1;
        if (m < LX) {
            const float2 sv = res[sw(c * 512 + k1)];
            const float2 cf = g_CF[m];
            y[(size_t)ch * LX + m] = sv.x * cf.x - sv.y * cf.y;
        }
    }
}

// ================= merged __global__ kernels ==================================

// init: bx==0 -> twiddle tables; bx in [1,512] -> chirp/phase tables block bx-1
__global__ void __launch_bounds__(256) k_init() {
    const int tid = threadIdx.x;
    if (blockIdx.x == 0) {
        for (int j = tid; j < 512; j += 256) {
            const double a = -2.0 * PI_D * (double)j;
            double s, c;
            sincos(a / 512.0, &s, &c);       g_T512[j] = make_float2((float)c, (float)s);
            sincos(a / (double)M1, &s, &c);  g_TM1[j]  = make_float2((float)c, (float)s);
            sincos(a / (double)M2, &s, &c);  g_TM2[j]  = make_float2((float)c, (float)s);
        }
        return;
    }
    const int i = (blockIdx.x - 1) * 256 + tid;   // < LX
    g_CX[i] = chirp(i, NN1, -1.f);
    {
        const float2 cf = chirp(i, NN2, 1.f);
        constexpr float INVM1 = 1.0f / (float)M1;
        g_CF[i] = make_float2(cf.x * INVM1, cf.y * INVM1);
    }
    if (i < KK) {
        const long long kk = (long long)i * i;
        const long long ra = (2LL * kk) % (2LL * NN1);
        const long long rb = kk % (2LL * NN2);
        const double ang = -(double)ra * (PI_D / (double)NN1)
                           + (double)rb * (PI_D / (double)NN2);
        float sn, cs;
        sincosf((float)ang, &sn, &cs);
        constexpr float SC0 = (float)(2.0 / ((double)NN2 * (double)M1 * (double)M2));
        const float sc = (i == 0 || i == KK - 1) ? 0.5f * SC0 : SC0;
        g_PC[i] = make_float2(cs * sc, sn * sc);
    }
}

// m1: [0,128) p1f(B1f)->bufA[0]; [128,256) p1f(Df)->bufA[M1];
//     [256,320) p1g B1h chirp -> bufA[2*M1]; [320,4416) p1g(h) -> hs1
__global__ void __launch_bounds__(256) k_m1(const float* __restrict__ h,
                                            float2* __restrict__ bufA,
                                            float2* __restrict__ hs1) {
    __shared__ float2 sA[2048], sB[2048], tw[512];
    const int tid = threadIdx.x;
    const int bx = blockIdx.x;
    if (bx < 128)       dev_p1f(bufA, bx, 0, sA, sB, tw, tid);
    else if (bx < 256)  dev_p1f(bufA, bx - 128, 1, sA, sB, tw, tid);
    else if (bx < 320)  dev_p1g<M2, 256, 4>(nullptr, bufA + 2 * (size_t)M1,
                                            bx - 256, 0, sA, sB, tw, tid);
    else {
        const int vb = bx - 320;
        dev_p1g<M2, 256, 1>(h, hs1, vb & 63, vb >> 6, sA, sB, tw, tid);
    }
}

// m2: [0,128) p2<M1>(bufA[0]->FM1[0]); [128,256) p2<M1>(bufA[M1]->FM1[M1]);
//     [256,384) p2<M2>(bufA[2*M1]->B1fh); [384,8576) p1g(x)->bufB
__global__ void __launch_bounds__(256) k_m2(const float* __restrict__ x,
                                            const float2* __restrict__ bufA,
                                            float2* __restrict__ FM1,
                                            float2* __restrict__ B1fh,
                                            float2* __restrict__ bufB) {
    __shared__ float2 sA[2048], sB[2048], tw[512];
    const int tid = threadIdx.x;
    const int bx = blockIdx.x;
    if (bx < 128)       dev_p2<M1, 512, false>(bufA, FM1, bx, sA, sB, tw, tid);
    else if (bx < 256)  dev_p2<M1, 512, false>(bufA + M1, FM1 + M1, bx - 128, sA, sB, tw, tid);
    else if (bx < 384)  dev_p2<M2, 256, false>(bufA + 2 * (size_t)M1, B1fh, bx - 256, sA, sB, tw, tid);
    else {
        const int vb = bx - 384;
        dev_p1g<M1, 512, 0>(x, bufB, vb & 127, vb >> 7, sA, sB, tw, tid);
    }
}

// m3: [0,8192) fusedM1<0>(bufB,*B1f -> bufA); [8192,12288) fusedM2(hs1,*B1fh -> hs2)
__global__ void __launch_bounds__(256) k_m3(const float2* __restrict__ bufB,
                                            const float2* __restrict__ FM1,
                                            float2* __restrict__ bufA,
                                            const float2* __restrict__ hs1,
                                            const float2* __restrict__ B1fh,
                                            float2* __restrict__ hs2) {
    __shared__ float2 sA[2048], sB[2048], tw[512];
    const int tid = threadIdx.x;
    const int bx = blockIdx.x;
    if (bx < 8192) {
        dev_fusedM1<0>(bufB, FM1, bufA, bx & 127, bx >> 7, sA, sB, tw, tid);
    } else {
        const int vb = bx - 8192;
        dev_fusedM2(hs1, B1fh, hs2, vb & 63, vb >> 6, sA, sB, tw, tid);
    }
}

// combine kernel (with h pass2 prefused): grid (128, NCH)
__global__ void __launch_bounds__(256) k_comb(const float2* __restrict__ in,
                                              const float2* __restrict__ hs2,
                                              float2* __restrict__ out) {
    __shared__ float2 sA[2048], sB[2048], tw[512], sH[4 * 136];
    dev_fusedComb(in, hs2, out, blockIdx.x, blockIdx.y, sA, sB, tw, sH, threadIdx.x);
}

// fusedM1<2>: grid (128, NCH)
__global__ void __launch_bounds__(256) k_f2(const float2* __restrict__ in,
                                            const float2* __restrict__ filt,
                                            float2* __restrict__ out) {
    __shared__ float2 sA[2048], sB[2048], tw[512];
    dev_fusedM1<2>(in, filt, out, blockIdx.x, blockIdx.y, sA, sB, tw, threadIdx.x);
}

// final pass: grid (128, NCH)
__global__ void __launch_bounds__(256) k_p2f(const float2* __restrict__ in,
                                             float* __restrict__ y) {
    __shared__ float2 sA[2048], sB[2048], tw[512];
    dev_p2f(in, y, blockIdx.x, blockIdx.y, sA, sB, tw, threadIdx.x);
}

// ---------------- launcher ---------------------------------------------------
extern "C" void kernel_launch(void* const* d_in, const int* in_sizes, int n_in,
                              void* d_out, int out_size) {
    const float* x = (const float*)d_in[0];
    const float* h = (const float*)d_in[1];
    float* y = (float*)d_out;

    float2 *bufA, *bufB, *bufC, *FM1, *B1fh;
    cudaGetSymbolAddress((void**)&bufA, g_bufA);
    cudaGetSymbolAddress((void**)&bufB, g_bufB);
    cudaGetSymbolAddress((void**)&bufC, g_bufC);
    cudaGetSymbolAddress((void**)&FM1,  g_FM1);
    cudaGetSymbolAddress((void**)&B1fh, g_B1fh);
    float2* hs1 = bufC;
    float2* hs2 = bufC + (size_t)NCH * M2;

    k_init<<<513, 256>>>();
    k_m1<<<320 + 64 * NCH, 256>>>(h, bufA, hs1);
    k_m2<<<384 + 128 * NCH, 256>>>(x, bufA, FM1, B1fh, bufB);
    k_m3<<<128 * NCH + 64 * NCH, 256>>>(bufB, FM1, bufA, hs1, B1fh, hs2);
    k_comb<<<dim3(128, NCH), 256>>>(bufA, hs2, bufB);
    k_f2<<<dim3(128, NCH), 256>>>(bufB, FM1 + M1, bufA);
    k_p2f<<<dim3(128, NCH), 256>>>(bufA, y);
}

// round 14
// speedup vs baseline: 2.3144x; 1.1678x over previous
#include <cuda_runtime.h>
#include <math.h>

// y = irfft(rfft(x, n=139263) * rfft(h, n=139263))[..., :131072]
// rfft grid N1=139263 (odd), irfft default grid N2=139262.
// y[m] = (2/N2) Re sum_{k<K} c_k X_k H_k e^{2pi i k m/N2}, c_0=c_{K-1}=1/2.
// Bluestein chirp-Z on pow2 FFTs (M1=2^18 for x & inverse, M2=2^17 for h).
// v5.1: L1-traffic diet. Chained twiddles (1 LDS/butterfly), global loads
// folded into FFT stage 1, pointwise multiplies folded into the next FFT's
// stage-1 load. 7 launches. (resubmission after infra-class bench failure;
// audited, no code delta vs v5)

#define LX 131072
#define LH 8192
#define KK 69632
#define M1 262144
#define M2 131072
#define NCH 64
#define NN1 139263LL
#define NN2 139262LL
#define PI_D 3.14159265358979323846264338327950288

__device__ float2 g_bufA[(size_t)NCH * M1];
__device__ float2 g_bufB[(size_t)NCH * M1];
__device__ float2 g_bufC[(size_t)NCH * M1];   // hs1 | hs2 (each NCH*M2)
__device__ float2 g_FM1[2 * M1];   // [0]=B1f spectrum, [1]=Df spectrum
__device__ float2 g_B1fh[M2];
__device__ float2 g_CX[LX];        // e^{-i pi n^2/N1}
__device__ float2 g_PC[KK];        // combine phase * scale
__device__ float2 g_CF[LX];        // e^{+i pi m^2/N2} / M1
__device__ float2 g_T512[512];
__device__ float2 g_TM1[512];
__device__ float2 g_TM2[512];

__device__ __forceinline__ float2 cmul(float2 a, float2 b) {
    return make_float2(a.x * b.x - a.y * b.y, a.x * b.y + a.y * b.x);
}
__device__ __forceinline__ float2 cadd(float2 a, float2 b) {
    return make_float2(a.x + b.x, a.y + b.y);
}
__device__ __forceinline__ float2 csub(float2 a, float2 b) {
    return make_float2(a.x - b.x, a.y - b.y);
}
__device__ __forceinline__ float2 chirp(long long u, long long nmod, float sgn) {
    const long long r = (u * u) % (2LL * nmod);
    const float ang = (float)((double)r * (PI_D / (double)nmod));
    float s, c;
    sincosf(ang, &s, &c);
    return make_float2(c, sgn * s);
}
__device__ __forceinline__ int sw(int i) { return i ^ ((i >> 4) & 15); }

// ---------------- register butterflies ---------------------------------------
template <bool INV>
__device__ __forceinline__ void dft4(float2& a, float2& b, float2& c, float2& d) {
    const float2 t0 = cadd(a, c), t1 = csub(a, c);
    const float2 t2 = cadd(b, d), t3 = csub(b, d);
    const float2 r = INV ? make_float2(-t3.y, t3.x) : make_float2(t3.y, -t3.x);
    a = cadd(t0, t2); b = cadd(t1, r); c = csub(t0, t2); d = csub(t1, r);
}
template <bool INV>
__device__ __forceinline__ void dft8(float2 v[8]) {
    float2 e0 = v[0], e1 = v[2], e2 = v[4], e3 = v[6];
    float2 o0 = v[1], o1 = v[3], o2 = v[5], o3 = v[7];
    dft4<INV>(e0, e1, e2, e3);
    dft4<INV>(o0, o1, o2, o3);
    const float r = 0.70710678118654752f;
    const float2 w1 = INV ? make_float2(r, r)  : make_float2(r, -r);
    const float2 w3 = INV ? make_float2(-r, r) : make_float2(-r, -r);
    o1 = cmul(o1, w1);
    o2 = INV ? make_float2(-o2.y, o2.x) : make_float2(o2.y, -o2.x);
    o3 = cmul(o3, w3);
    v[0] = cadd(e0, o0); v[4] = csub(e0, o0);
    v[1] = cadd(e1, o1); v[5] = csub(e1, o1);
    v[2] = cadd(e2, o2); v[6] = csub(e2, o2);
    v[3] = cadd(e3, o3); v[7] = csub(e3, o3);
}

// ---------------- Stockham stages with chained twiddles ----------------------
// w_m = (w^p)^m == tw[(p*m)<<(9-L2N)]; only 1 twiddle LDS per butterfly.
template <bool INV, int L2S, int L2N, int LEN, int LPF>
__device__ __forceinline__ void st8(const float2* __restrict__ s, float2* __restrict__ d,
                                    const float2* __restrict__ tw, int go, int lane) {
    constexpr int NB = LEN / 8;
    constexpr int NIT = (NB + LPF - 1) / LPF;
#pragma unroll
    for (int it = 0; it < NIT; it++) {
        const int bf = it * LPF + lane;
        if (LPF > NB && bf >= NB) continue;
        const int p = bf >> L2S;
        const int q = bf & ((1 << L2S) - 1);
        float2 v[8];
#pragma unroll
        for (int m = 0; m < 8; m++) v[m] = s[go + sw(bf + m * NB)];
        dft8<INV>(v);
        const int ob = q + (p << (L2S + 3));
        d[go + sw(ob)] = v[0];
        if (L2N == 3) {
#pragma unroll
            for (int m = 1; m < 8; m++) d[go + sw(ob + (m << L2S))] = v[m];
        } else {
            float2 w1 = tw[p << (9 - L2N)];
            if (INV) w1.y = -w1.y;
            float2 wm = w1;
            d[go + sw(ob + (1 << L2S))] = cmul(wm, v[1]);
#pragma unroll
            for (int m = 2; m < 8; m++) {
                wm = cmul(wm, w1);
                d[go + sw(ob + (m << L2S))] = cmul(wm, v[m]);
            }
        }
    }
}
template <bool INV, int L2S, int LEN, int LPF>
__device__ __forceinline__ void st4(const float2* __restrict__ s, float2* __restrict__ d,
                                    int go, int lane) {
    constexpr int NB = LEN / 4;
    constexpr int NIT = (NB + LPF - 1) / LPF;
#pragma unroll
    for (int it = 0; it < NIT; it++) {
        const int bf = it * LPF + lane;
        if (LPF > NB && bf >= NB) continue;
        float2 a = s[go + sw(bf)];
        float2 b = s[go + sw(bf + NB)];
        float2 c = s[go + sw(bf + 2 * NB)];
        float2 e = s[go + sw(bf + 3 * NB)];
        dft4<INV>(a, b, c, e);
        d[go + sw(bf)] = a;
        d[go + sw(bf + (1 << L2S))] = b;
        d[go + sw(bf + (2 << L2S))] = c;
        d[go + sw(bf + (3 << L2S))] = e;
    }
}

// stage 1 (L2S=0) fed by a functor (global load or SMEM-with-multiply).
// Our uses always have NB <= LPF, so one guarded iteration suffices.
template <bool INV, int LEN, int LPF, class F>
__device__ __forceinline__ void st8_f(F f, float2* __restrict__ d,
                                      const float2* __restrict__ tw, int go, int lane) {
    constexpr int NB = LEN / 8;
    if (LPF > NB && lane >= NB) return;
    const int bf = lane;
    float2 v[8];
#pragma unroll
    for (int m = 0; m < 8; m++) v[m] = f(bf + m * NB);
    dft8<INV>(v);
    const int ob = bf * 8;
    constexpr int TSH = (LEN == 512) ? 0 : 1;
    d[go + sw(ob)] = v[0];
    float2 w1 = tw[bf << TSH];
    if (INV) w1.y = -w1.y;
    float2 wm = w1;
    d[go + sw(ob + 1)] = cmul(wm, v[1]);
#pragma unroll
    for (int m = 2; m < 8; m++) {
        wm = cmul(wm, w1);
        d[go + sw(ob + m)] = cmul(wm, v[m]);
    }
}

// remaining stages after stage 1; result ends in r.
template <bool INV, int LPF>
__device__ __forceinline__ void fft512_rest(float2* r, float2* t,
                                            const float2* tw, int go, int lane) {
    __syncthreads();
    st8<INV, 3, 6, 512, LPF>(r, t, tw, go, lane); __syncthreads();
    st8<INV, 6, 3, 512, LPF>(t, r, tw, go, lane); __syncthreads();
}
template <bool INV, int LPF>
__device__ __forceinline__ void fft256_rest(float2* r, float2* t,
                                            const float2* tw, int go, int lane) {
    __syncthreads();
    st8<INV, 3, 5, 256, LPF>(r, t, tw, go, lane); __syncthreads();
    st4<INV, 6, 256, LPF>(t, r, go, lane); __syncthreads();
}

// classic path for precompute/prep kernels; result ALWAYS in B.
template <int LEN, int NFFT, bool INV>
__device__ __forceinline__ float2* block_fft8(float2* A, float2* B, const float2* tw, int tid) {
    constexpr int LPF = 256 / NFFT;
    const int g = tid / LPF, lane = tid % LPF;
    const int go = g * LEN;
    if constexpr (LEN == 512) {
        st8<INV, 0, 9, 512, LPF>(A, B, tw, go, lane); __syncthreads();
        st8<INV, 3, 6, 512, LPF>(B, A, tw, go, lane); __syncthreads();
        st8<INV, 6, 3, 512, LPF>(A, B, tw, go, lane); __syncthreads();
    } else {
        st8<INV, 0, 8, 256, LPF>(A, B, tw, go, lane); __syncthreads();
        st8<INV, 3, 5, 256, LPF>(B, A, tw, go, lane); __syncthreads();
        st4<INV, 6, 256, LPF>(A, B, go, lane); __syncthreads();
    }
    return B;
}

template <int MSZ>
__device__ __forceinline__ float2 wM(unsigned a, bool conj) {
    constexpr int HS = (512 * 512) / MSZ;
    const float2* lo = (MSZ == M1) ? g_TM1 : g_TM2;
    float2 w = cmul(g_T512[(a >> 9) * HS], lo[a & 511]);
    if (conj) w.y = -w.y;
    return w;
}

__device__ __forceinline__ void load_tw(float2* tw, int tid) {
    for (int j = tid; j < 512; j += 256) tw[j] = g_T512[j];
}

// ================= device pass bodies =========================================

// pass1 with generated input. MODE: 0=x(M1), 1=h(M2), 4=B1h chirp(M2)
template <int MSZ, int NA, int MODE>
__device__ void dev_p1g(const float* __restrict__ src, float2* __restrict__ out,
                        int bx, int ch, float2* sA, float2* sB, float2* tw, int tid) {
    out += (size_t)ch * MSZ;
    const int colbase = bx * 4;
    load_tw(tw, tid);
    for (int i = tid; i < 4 * 512; i += 256) {
        const int c = i & 3, t = i >> 2;
        const int n = (colbase + c) + NA * t;
        float2 v = make_float2(0.f, 0.f);
        if (MODE == 0) {
            if (n < LX) {
                const float xv = src[(size_t)ch * LX + n];
                const float2 cc = g_CX[n];
                v = make_float2(xv * cc.x, xv * cc.y);
            }
        } else if (MODE == 1) {
            if (n < LH) {
                const float hv = src[(size_t)ch * LH + n];
                const float2 cc = g_CX[n];
                v = make_float2(hv * cc.x, hv * cc.y);
            }
        } else {
            if (n < KK)                 v = chirp(n, NN1, 1.f);
            else if (n >= M2 - LH + 1)  v = chirp((long long)(M2 - n), NN1, 1.f);
        }
        sA[sw(c * 512 + t)] = v;
    }
    __syncthreads();
    float2* res = block_fft8<512, 4, false>(sA, sB, tw, tid);
    for (int i = tid; i < 4 * 512; i += 256) {
        const int c = i & 3, k2 = i >> 2;
        const int col = colbase + c;
        out[(size_t)k2 * NA + col] =
            cmul(res[sw(c * 512 + k2)], wM<MSZ>((unsigned)(col * k2), false));
    }
}

// filter generator pass1 (M1): which: 0 -> chirp b (N1), 1 -> chirp d (N2)
__device__ void dev_p1f(float2* __restrict__ out, int bx, int which,
                        float2* sA, float2* sB, float2* tw, int tid) {
    out += (size_t)which * M1;
    const int colbase = bx * 4;
    load_tw(tw, tid);
    for (int i = tid; i < 4 * 512; i += 256) {
        const int c = i & 3, t = i >> 2;
        const int n = (colbase + c) + 512 * t;
        float2 v = make_float2(0.f, 0.f);
        if (which == 0) {
            if (n < KK)                 v = chirp(n, NN1, 1.f);
            else if (n >= M1 - LX + 1)  v = chirp((long long)(M1 - n), NN1, 1.f);
        } else {
            if (n < LX)                 v = chirp(n, NN2, -1.f);
            else if (n >= M1 - KK + 1)  v = chirp((long long)(M1 - n), NN2, -1.f);
        }
        sA[sw(c * 512 + t)] = v;
    }
    __syncthreads();
    float2* res = block_fft8<512, 4, false>(sA, sB, tw, tid);
    for (int i = tid; i < 4 * 512; i += 256) {
        const int c = i & 3, k2 = i >> 2;
        const int col = colbase + c;
        out[(size_t)k2 * 512 + col] =
            cmul(res[sw(c * 512 + k2)], wM<M1>((unsigned)(col * k2), false));
    }
}

// plain pass2 (natural-order output)
template <int MSZ, int NA, bool INV>
__device__ void dev_p2(const float2* __restrict__ in, float2* __restrict__ out,
                       int bx, float2* sA, float2* sB, float2* tw, int tid) {
    const int rowbase = bx * 4;
    load_tw(tw, tid);
    for (int i = tid; i < 4 * NA; i += 256) {
        const int c = i / NA, n1 = i % NA;
        sA[sw(c * NA + n1)] = in[(size_t)(rowbase + c) * NA + n1];
    }
    __syncthreads();
    float2* res = block_fft8<NA, 4, INV>(sA, sB, tw, tid);
    constexpr int NROW = MSZ / NA;
    for (int i = tid; i < 4 * NA; i += 256) {
        const int c = i & 3, k1 = i >> 2;
        out[(size_t)(rowbase + c) + NROW * k1] = res[sw(c * NA + k1)];
    }
}

// fused M1: FFT512(fwd, loads global) -> *filt (folded) -> FFT512(inv) -> out
__device__ void dev_fusedM1(const float2* __restrict__ in, const float2* __restrict__ filt,
                            float2* __restrict__ out, int bx, int ch,
                            float2* sA, float2* sB, float2* tw, int tid) {
    in  += (size_t)ch * M1;
    out += (size_t)ch * M1;
    const int rowbase = bx * 4;
    const int g = tid >> 6, lane = tid & 63, go = g * 512;
    load_tw(tw, tid);
    __syncthreads();
    const float2* gp = in + (size_t)(rowbase + g) * 512;
    st8_f<false, 512, 64>([&](int idx) { return gp[idx]; }, sB, tw, go, lane);
    fft512_rest<false, 64>(sB, sA, tw, go, lane);          // result in sB
    const int kb = rowbase + g;
    st8_f<true, 512, 64>([&](int idx) {
        return cmul(sB[go + sw(idx)], filt[kb + 512 * idx]);
    }, sA, tw, go, lane);
    fft512_rest<true, 64>(sA, sB, tw, go, lane);           // result in sA
    for (int i = tid; i < 2048; i += 256) {
        const int c = i & 3, k2p = i >> 2;
        const int col = rowbase + c;
        out[(size_t)k2p * 512 + col] =
            cmul(sA[c * 512 + sw(k2p)], wM<M1>((unsigned)(col * k2p), true));
    }
}

// fused combine: FFT256(inv of hs2 rows, folded load) -> sH;
// FFT512(inv, loads global) -> combine(sH,g_PC) folded -> FFT512(fwd) -> out
__device__ void dev_fusedComb(const float2* __restrict__ in, const float2* __restrict__ hs2,
                              float2* __restrict__ out, int bx, int ch,
                              float2* sA, float2* sB, float2* tw, float2* sH, int tid) {
    in  += (size_t)ch * M1;
    out += (size_t)ch * M1;
    hs2 += (size_t)ch * M2;
    const int rowbase = bx * 4;
    const int g = tid >> 6, lane = tid & 63;
    load_tw(tw, tid);
    __syncthreads();
    // --- step A: H rows (4 FFT-256, lanes >=32 idle in stage1) ---
    {
        const int goH = g * 256;
        const float2* hp = hs2 + (size_t)(rowbase + g) * 256;
        st8_f<true, 256, 64>([&](int idx) { return hp[idx]; }, sB, tw, goH, lane);
        fft256_rest<true, 64>(sB, sA, tw, goH, lane);      // result in sB
        for (int i = tid; i < 4 * 136; i += 256) {
            const int c = i / 136, k1 = i % 136;
            sH[c * 136 + k1] = sB[c * 256 + sw(k1)];
        }
        __syncthreads();
    }
    // --- step B ---
    const int go = g * 512;
    const float2* gp = in + (size_t)(rowbase + g) * 512;
    st8_f<true, 512, 64>([&](int idx) { return gp[idx]; }, sB, tw, go, lane);
    fft512_rest<true, 64>(sB, sA, tw, go, lane);           // result in sB
    const int kb = rowbase + g;
    st8_f<false, 512, 64>([&](int idx) {
        float2 v = make_float2(0.f, 0.f);
        if (idx < 136) {
            v = cmul(cmul(sB[go + sw(idx)], sH[g * 136 + idx]), g_PC[kb + 512 * idx]);
        }
        return v;
    }, sA, tw, go, lane);
    fft512_rest<false, 64>(sA, sB, tw, go, lane);          // result in sA
    for (int i = tid; i < 2048; i += 256) {
        const int c = i & 3, k2p = i >> 2;
        const int col = rowbase + c;
        out[(size_t)k2p * 512 + col] =
            cmul(sA[c * 512 + sw(k2p)], wM<M1>((unsigned)(col * k2p), false));
    }
}

// fused M2: FFT256(fwd, loads global rows) -> reorg+*B1fh folded -> FFT512(inv) -> out
__device__ void dev_fusedM2(const float2* __restrict__ in, const float2* __restrict__ filt,
                            float2* __restrict__ out, int bx, int ch,
                            float2* sA, float2* sB, float2* tw, int tid) {
    in  += (size_t)ch * M2;
    out += (size_t)ch * M2;
    const int r = bx * 4;
    load_tw(tw, tid);
    __syncthreads();
    // first FFT: 8 transforms of 256
    {
        const int g8 = tid >> 5, lane8 = tid & 31, go8 = g8 * 256;
        const int row = r + (g8 & 3) + 256 * (g8 >> 2);
        const float2* gp = in + (size_t)row * 256;
        st8_f<false, 256, 32>([&](int idx) { return gp[idx]; }, sB, tw, go8, lane8);
        fft256_rest<false, 32>(sB, sA, tw, go8, lane8);    // result in sB
    }
    // second FFT: 4 transforms of 512 with reorg+filter folded into stage 1
    const int c0 = tid >> 6, lane4 = tid & 63, go4 = c0 * 512;
    st8_f<true, 512, 64>([&](int idx) {
        const int k1 = idx >> 1, hi = idx & 1;
        const int k = (r + c0 + 256 * hi) + 512 * k1;
        return cmul(sB[(c0 + 4 * hi) * 256 + sw(k1)], filt[k]);
    }, sA, tw, go4, lane4);
    fft512_rest<true, 64>(sA, sB, tw, go4, lane4);         // result in sA
    for (int i = tid; i < 2048; i += 256) {
        const int c = i & 3, k2p = i >> 2;
        const int col = r + c;
        out[(size_t)k2p * 256 + col] =
            cmul(sA[c * 512 + sw(k2p)], wM<M2>((unsigned)(col * k2p), true));
    }
}

// final: FFT512(inv, loads global) -> chirp(g_CF) -> real output
__device__ void dev_p2f(const float2* __restrict__ in, float* __restrict__ y,
                        int bx, int ch, float2* sA, float2* sB, float2* tw, int tid) {
    in += (size_t)ch * M1;
    const int rowbase = bx * 4;
    const int g = tid >> 6, lane = tid & 63, go = g * 512;
    load_tw(tw, tid);
    __syncthreads();
    const float2* gp = in + (size_t)(rowbase + g) * 512;
    st8_f<true, 512, 64>([&](int idx) { return gp[idx]; }, sB, tw, go, lane);
    fft512_rest<true, 64>(sB, sA, tw, go, lane);           // result in sB
    for (int i = tid; i < 2048; i += 256) {
        const int c = i & 3, k1 = i >> 2;
        const int m = (rowbase + c) + 512 * k1;
        if (m < LX) {
            const float2 sv = sB[c * 512 + sw(k1)];
            const float2 cf = g_CF[m];
            y[(size_t)ch * LX + m] = sv.x * cf.x - sv.y * cf.y;
        }
    }
}

// ================= merged __global__ kernels ==================================

__global__ void __launch_bounds__(256) k_init() {
    const int tid = threadIdx.x;
    if (blockIdx.x == 0) {
        for (int j = tid; j < 512; j += 256) {
            const double a = -2.0 * PI_D * (double)j;
            double s, c;
            sincos(a / 512.0, &s, &c);       g_T512[j] = make_float2((float)c, (float)s);
            sincos(a / (double)M1, &s, &c);  g_TM1[j]  = make_float2((float)c, (float)s);
            sincos(a / (double)M2, &s, &c);  g_TM2[j]  = make_float2((float)c, (float)s);
        }
        return;
    }
    const int i = (blockIdx.x - 1) * 256 + tid;   // < LX
    g_CX[i] = chirp(i, NN1, -1.f);
    {
        const float2 cf = chirp(i, NN2, 1.f);
        constexpr float INVM1 = 1.0f / (float)M1;
        g_CF[i] = make_float2(cf.x * INVM1, cf.y * INVM1);
    }
    if (i < KK) {
        const long long kk = (long long)i * i;
        const long long ra = (2LL * kk) % (2LL * NN1);
        const long long rb = kk % (2LL * NN2);
        const double ang = -(double)ra * (PI_D / (double)NN1)
                           + (double)rb * (PI_D / (double)NN2);
        float sn, cs;
        sincosf((float)ang, &sn, &cs);
        constexpr float SC0 = (float)(2.0 / ((double)NN2 * (double)M1 * (double)M2));
        const float sc = (i == 0 || i == KK - 1) ? 0.5f * SC0 : SC0;
        g_PC[i] = make_float2(cs * sc, sn * sc);
    }
}

__global__ void __launch_bounds__(256) k_m1(const float* __restrict__ h,
                                            float2* __restrict__ bufA,
                                            float2* __restrict__ hs1) {
    __shared__ float2 sA[2048], sB[2048], tw[512];
    const int tid = threadIdx.x;
    const int bx = blockIdx.x;
    if (bx < 128)       dev_p1f(bufA, bx, 0, sA, sB, tw, tid);
    else if (bx < 256)  dev_p1f(bufA, bx - 128, 1, sA, sB, tw, tid);
    else if (bx < 320)  dev_p1g<M2, 256, 4>(nullptr, bufA + 2 * (size_t)M1,
                                            bx - 256, 0, sA, sB, tw, tid);
    else {
        const int vb = bx - 320;
        dev_p1g<M2, 256, 1>(h, hs1, vb & 63, vb >> 6, sA, sB, tw, tid);
    }
}

__global__ void __launch_bounds__(256) k_m2(const float* __restrict__ x,
                                            const float2* __restrict__ bufA,
                                            float2* __restrict__ FM1,
                                            float2* __restrict__ B1fh,
                                            float2* __restrict__ bufB) {
    __shared__ float2 sA[2048], sB[2048], tw[512];
    const int tid = threadIdx.x;
    const int bx = blockIdx.x;
    if (bx < 128)       dev_p2<M1, 512, false>(bufA, FM1, bx, sA, sB, tw, tid);
    else if (bx < 256)  dev_p2<M1, 512, false>(bufA + M1, FM1 + M1, bx - 128, sA, sB, tw, tid);
    else if (bx < 384)  dev_p2<M2, 256, false>(bufA + 2 * (size_t)M1, B1fh, bx - 256, sA, sB, tw, tid);
    else {
        const int vb = bx - 384;
        dev_p1g<M1, 512, 0>(x, bufB, vb & 127, vb >> 7, sA, sB, tw, tid);
    }
}

__global__ void __launch_bounds__(256) k_m3(const float2* __restrict__ bufB,
                                            const float2* __restrict__ FM1,
                                            float2* __restrict__ bufA,
                                            const float2* __restrict__ hs1,
                                            const float2* __restrict__ B1fh,
                                            float2* __restrict__ hs2) {
    __shared__ float2 sA[2048], sB[2048], tw[512];
    const int tid = threadIdx.x;
    const int bx = blockIdx.x;
    if (bx < 8192) {
        dev_fusedM1(bufB, FM1, bufA, bx & 127, bx >> 7, sA, sB, tw, tid);
    } else {
        const int vb = bx - 8192;
        dev_fusedM2(hs1, B1fh, hs2, vb & 63, vb >> 6, sA, sB, tw, tid);
    }
}

__global__ void __launch_bounds__(256) k_comb(const float2* __restrict__ in,
                                              const float2* __restrict__ hs2,
                                              float2* __restrict__ out) {
    __shared__ float2 sA[2048], sB[2048], tw[512], sH[4 * 136];
    dev_fusedComb(in, hs2, out, blockIdx.x, blockIdx.y, sA, sB, tw, sH, threadIdx.x);
}

__global__ void __launch_bounds__(256) k_f2(const float2* __restrict__ in,
                                            const float2* __restrict__ filt,
                                            float2* __restrict__ out) {
    __shared__ float2 sA[2048], sB[2048], tw[512];
    dev_fusedM1(in, filt, out, blockIdx.x, blockIdx.y, sA, sB, tw, threadIdx.x);
}

__global__ void __launch_bounds__(256) k_p2f(const float2* __restrict__ in,
                                             float* __restrict__ y) {
    __shared__ float2 sA[2048], sB[2048], tw[512];
    dev_p2f(in, y, blockIdx.x, blockIdx.y, sA, sB, tw, threadIdx.x);
}

// ---------------- launcher ---------------------------------------------------
extern "C" void kernel_launch(void* const* d_in, const int* in_sizes, int n_in,
                              void* d_out, int out_size) {
    const float* x = (const float*)d_in[0];
    const float* h = (const float*)d_in[1];
    float* y = (float*)d_out;

    float2 *bufA, *bufB, *bufC, *FM1, *B1fh;
    cudaGetSymbolAddress((void**)&bufA, g_bufA);
    cudaGetSymbolAddress((void**)&bufB, g_bufB);
    cudaGetSymbolAddress((void**)&bufC, g_bufC);
    cudaGetSymbolAddress((void**)&FM1,  g_FM1);
    cudaGetSymbolAddress((void**)&B1fh, g_B1fh);
    float2* hs1 = bufC;
    float2* hs2 = bufC + (size_t)NCH * M2;

    k_init<<<513, 256>>>();
    k_m1<<<320 + 64 * NCH, 256>>>(h, bufA, hs1);
    k_m2<<<384 + 128 * NCH, 256>>>(x, bufA, FM1, B1fh, bufB);
    k_m3<<<128 * NCH + 64 * NCH, 256>>>(bufB, FM1, bufA, hs1, B1fh, hs2);
    k_comb<<<dim3(128, NCH), 256>>>(bufA, hs2, bufB);
    k_f2<<<dim3(128, NCH), 256>>>(bufB, FM1 + M1, bufA);
    k_p2f<<<dim3(128, NCH), 256>>>(bufA, y);
}

// round 16
// speedup vs baseline: 3.2599x; 1.4085x over previous
#include <cuda_runtime.h>
#include <math.h>

// y = irfft(rfft(x, n=139263) * rfft(h, n=139263))[..., :131072]
// rfft grid N1=139263 (odd), irfft default grid N2=139262.
// y[m] = (2/N2) Re sum_{k<K} c_k X_k H_k e^{2pi i k m/N2}, c_0=c_{K-1}=1/2.
// Bluestein chirp-Z on pow2 FFTs (M1=2^18 for x & inverse, M2=2^17 for h).
// v6.1: register-resident FFT512 (2 SMEM exchanges; filter multiplies in regs),
// transposed filter/phase tables (coalesced gathers), chained output twiddles,
// float4 x loads, half-zero prep shortcuts. 7 launches.
// (resubmission after infra-class bench failure; audited, no code delta vs v6)

#define LX 131072
#define LH 8192
#define KK 69632
#define M1 262144
#define M2 131072
#define NCH 64
#define NN1 139263LL
#define NN2 139262LL
#define PI_D 3.14159265358979323846264338327950288

__device__ float2 g_bufA[(size_t)NCH * M1];
__device__ float2 g_bufB[(size_t)NCH * M1];
__device__ float2 g_bufC[(size_t)NCH * M1];   // hs1 | hs2 (each NCH*M2)
__device__ float2 g_FM1[2 * M1];   // TRANSPOSED: [which][colLow*512 + kHigh]
__device__ float2 g_B1fh[M2];      // TRANSPOSED: [rowLow*256 + kHigh]
__device__ float2 g_CX[LX];        // e^{-i pi n^2/N1} (natural)
__device__ float2 g_PCT[KK];       // combine phase*scale TRANSPOSED [kLow*136+kHigh]
__device__ float2 g_CFT[LX];       // final chirp/M1 TRANSPOSED [mLow*256+mHigh]
__device__ float2 g_T512[512];
__device__ float2 g_TM1[512];
__device__ float2 g_TM2[512];

__device__ __forceinline__ float2 cmul(float2 a, float2 b) {
    return make_float2(a.x * b.x - a.y * b.y, a.x * b.y + a.y * b.x);
}
__device__ __forceinline__ float2 cadd(float2 a, float2 b) {
    return make_float2(a.x + b.x, a.y + b.y);
}
__device__ __forceinline__ float2 csub(float2 a, float2 b) {
    return make_float2(a.x - b.x, a.y - b.y);
}
__device__ __forceinline__ float2 chirp(long long u, long long nmod, float sgn) {
    const long long r = (u * u) % (2LL * nmod);
    const float ang = (float)((double)r * (PI_D / (double)nmod));
    float s, c;
    sincosf(ang, &s, &c);
    return make_float2(c, sgn * s);
}
__device__ __forceinline__ int sw(int i) { return i ^ ((i >> 4) & 15); }

template <bool INV>
__device__ __forceinline__ void dft4(float2& a, float2& b, float2& c, float2& d) {
    const float2 t0 = cadd(a, c), t1 = csub(a, c);
    const float2 t2 = cadd(b, d), t3 = csub(b, d);
    const float2 r = INV ? make_float2(-t3.y, t3.x) : make_float2(t3.y, -t3.x);
    a = cadd(t0, t2); b = cadd(t1, r); c = csub(t0, t2); d = csub(t1, r);
}
template <bool INV>
__device__ __forceinline__ void dft8(float2 v[8]) {
    float2 e0 = v[0], e1 = v[2], e2 = v[4], e3 = v[6];
    float2 o0 = v[1], o1 = v[3], o2 = v[5], o3 = v[7];
    dft4<INV>(e0, e1, e2, e3);
    dft4<INV>(o0, o1, o2, o3);
    const float r = 0.70710678118654752f;
    const float2 w1 = INV ? make_float2(r, r)  : make_float2(r, -r);
    const float2 w3 = INV ? make_float2(-r, r) : make_float2(-r, -r);
    o1 = cmul(o1, w1);
    o2 = INV ? make_float2(-o2.y, o2.x) : make_float2(o2.y, -o2.x);
    o3 = cmul(o3, w3);
    v[0] = cadd(e0, o0); v[4] = csub(e0, o0);
    v[1] = cadd(e1, o1); v[5] = csub(e1, o1);
    v[2] = cadd(e2, o2); v[6] = csub(e2, o2);
    v[3] = cadd(e3, o3); v[7] = csub(e3, o3);
}

// -------- old-style SMEM stages (kept for FFT256 parts + precompute) ---------
template <bool INV, int L2S, int L2N, int LEN, int LPF>
__device__ __forceinline__ void st8(const float2* __restrict__ s, float2* __restrict__ d,
                                    const float2* __restrict__ tw, int go, int lane) {
    constexpr int NB = LEN / 8;
    constexpr int NIT = (NB + LPF - 1) / LPF;
#pragma unroll
    for (int it = 0; it < NIT; it++) {
        const int bf = it * LPF + lane;
        if (LPF > NB && bf >= NB) continue;
        const int p = bf >> L2S;
        const int q = bf & ((1 << L2S) - 1);
        float2 v[8];
#pragma unroll
        for (int m = 0; m < 8; m++) v[m] = s[go + sw(bf + m * NB)];
        dft8<INV>(v);
        const int ob = q + (p << (L2S + 3));
        d[go + sw(ob)] = v[0];
        if (L2N == 3) {
#pragma unroll
            for (int m = 1; m < 8; m++) d[go + sw(ob + (m << L2S))] = v[m];
        } else {
            float2 w1 = tw[p << (9 - L2N)];
            if (INV) w1.y = -w1.y;
            float2 wm = w1;
            d[go + sw(ob + (1 << L2S))] = cmul(wm, v[1]);
#pragma unroll
            for (int m = 2; m < 8; m++) {
                wm = cmul(wm, w1);
                d[go + sw(ob + (m << L2S))] = cmul(wm, v[m]);
            }
        }
    }
}
template <bool INV, int L2S, int LEN, int LPF>
__device__ __forceinline__ void st4(const float2* __restrict__ s, float2* __restrict__ d,
                                    int go, int lane) {
    constexpr int NB = LEN / 4;
    constexpr int NIT = (NB + LPF - 1) / LPF;
#pragma unroll
    for (int it = 0; it < NIT; it++) {
        const int bf = it * LPF + lane;
        if (LPF > NB && bf >= NB) continue;
        float2 a = s[go + sw(bf)];
        float2 b = s[go + sw(bf + NB)];
        float2 c = s[go + sw(bf + 2 * NB)];
        float2 e = s[go + sw(bf + 3 * NB)];
        dft4<INV>(a, b, c, e);
        d[go + sw(bf)] = a;
        d[go + sw(bf + (1 << L2S))] = b;
        d[go + sw(bf + (2 << L2S))] = c;
        d[go + sw(bf + (3 << L2S))] = e;
    }
}
template <bool INV, int LEN, int LPF, class F>
__device__ __forceinline__ void st8_f(F f, float2* __restrict__ d,
                                      const float2* __restrict__ tw, int go, int lane) {
    constexpr int NB = LEN / 8;
    if (LPF > NB && lane >= NB) return;
    const int bf = lane;
    float2 v[8];
#pragma unroll
    for (int m = 0; m < 8; m++) v[m] = f(bf + m * NB);
    dft8<INV>(v);
    const int ob = bf * 8;
    constexpr int TSH = (LEN == 512) ? 0 : 1;
    d[go + sw(ob)] = v[0];
    float2 w1 = tw[bf << TSH];
    if (INV) w1.y = -w1.y;
    float2 wm = w1;
    d[go + sw(ob + 1)] = cmul(wm, v[1]);
#pragma unroll
    for (int m = 2; m < 8; m++) {
        wm = cmul(wm, w1);
        d[go + sw(ob + m)] = cmul(wm, v[m]);
    }
}
template <bool INV, int LPF>
__device__ __forceinline__ void fft256_rest(float2* r, float2* t,
                                            const float2* tw, int go, int lane) {
    __syncthreads();
    st8<INV, 3, 5, 256, LPF>(r, t, tw, go, lane); __syncthreads();
    st4<INV, 6, 256, LPF>(t, r, go, lane); __syncthreads();
}
template <int LEN, int NFFT, bool INV>
__device__ __forceinline__ float2* block_fft8(float2* A, float2* B, const float2* tw, int tid) {
    constexpr int LPF = 256 / NFFT;
    const int g = tid / LPF, lane = tid % LPF;
    const int go = g * LEN;
    if constexpr (LEN == 512) {
        st8<INV, 0, 9, 512, LPF>(A, B, tw, go, lane); __syncthreads();
        st8<INV, 3, 6, 512, LPF>(B, A, tw, go, lane); __syncthreads();
        st8<INV, 6, 3, 512, LPF>(A, B, tw, go, lane); __syncthreads();
    } else {
        st8<INV, 0, 8, 256, LPF>(A, B, tw, go, lane); __syncthreads();
        st8<INV, 3, 5, 256, LPF>(B, A, tw, go, lane); __syncthreads();
        st4<INV, 6, 256, LPF>(A, B, go, lane); __syncthreads();
    }
    return B;
}

// -------- register-resident FFT512: v[m]=x[lane+64m] in, X[lane+64m] out -----
// Two SMEM exchanges (x1 then x2); one sync per exchange. 64 lanes per FFT.
template <bool INV>
__device__ __forceinline__ void rfft512(float2 v[8], float2* x1, float2* x2,
                                        const float2* tw, int go, int lane) {
    dft8<INV>(v);
    {
        float2 w1 = tw[lane];
        if (INV) w1.y = -w1.y;
        float2 wm = w1;
        x1[go + sw(8 * lane)] = v[0];
        x1[go + sw(8 * lane + 1)] = cmul(wm, v[1]);
#pragma unroll
        for (int m = 2; m < 8; m++) { wm = cmul(wm, w1); x1[go + sw(8 * lane + m)] = cmul(wm, v[m]); }
    }
    __syncthreads();
#pragma unroll
    for (int m = 0; m < 8; m++) v[m] = x1[go + sw(lane + 64 * m)];
    dft8<INV>(v);
    {
        const int p = lane >> 3, q = lane & 7;
        float2 w2 = tw[p << 3];
        if (INV) w2.y = -w2.y;
        float2 wm = w2;
        const int ob = q + (p << 6);
        x2[go + sw(ob)] = v[0];
        x2[go + sw(ob + 8)] = cmul(wm, v[1]);
#pragma unroll
        for (int m = 2; m < 8; m++) { wm = cmul(wm, w2); x2[go + sw(ob + 8 * m)] = cmul(wm, v[m]); }
    }
    __syncthreads();
#pragma unroll
    for (int m = 0; m < 8; m++) v[m] = x2[go + sw(lane + 64 * m)];
    dft8<INV>(v);   // final stage p==0: no twiddle; v[m] = X[lane+64m]
}

template <int MSZ>
__device__ __forceinline__ float2 wM(unsigned a, bool conj) {
    constexpr int HS = (512 * 512) / MSZ;
    const float2* lo = (MSZ == M1) ? g_TM1 : g_TM2;
    float2 w = cmul(g_T512[(a >> 9) * HS], lo[a & 511]);
    if (conj) w.y = -w.y;
    return w;
}
__device__ __forceinline__ void load_tw(float2* tw, int tid) {
    for (int j = tid; j < 512; j += 256) tw[j] = g_T512[j];
}

// ================= device pass bodies =========================================

// x-prep pass1 (M1): float4-coalesced load, half-zero (t<256), reg FFT.
__device__ void dev_p1x(const float* __restrict__ x, float2* __restrict__ out,
                        int bx, int ch, float2* sA, float2* sB, float2* tw, int tid) {
    out += (size_t)ch * M1;
    const int colbase = bx * 4;
    const int g = tid >> 6, lane = tid & 63, go = g * 512;
    load_tw(tw, tid);
    {   // stage x*cx for t = tid (0..255), 4 columns per load
        const int t = tid;
        const int n = colbase + 512 * t;
        const float4 xv = *reinterpret_cast<const float4*>(x + (size_t)ch * LX + n);
        const float4 ca = reinterpret_cast<const float4*>(g_CX)[n >> 1];
        const float4 cb = reinterpret_cast<const float4*>(g_CX)[(n >> 1) + 1];
        sA[0 * 256 + sw(t)] = make_float2(xv.x * ca.x, xv.x * ca.y);
        sA[1 * 256 + sw(t)] = make_float2(xv.y * ca.z, xv.y * ca.w);
        sA[2 * 256 + sw(t)] = make_float2(xv.z * cb.x, xv.z * cb.y);
        sA[3 * 256 + sw(t)] = make_float2(xv.w * cb.z, xv.w * cb.w);
    }
    __syncthreads();
    float2 v[8];
#pragma unroll
    for (int m = 0; m < 8; m++)
        v[m] = (m < 4) ? sA[g * 256 + sw(lane + 64 * m)] : make_float2(0.f, 0.f);
    rfft512<false>(v, sB, sA, tw, go, lane);
    const int col = colbase + g;
    float2 w = wM<M1>((unsigned)(col * lane), false);
    const float2 ws = wM<M1>((unsigned)(64 * col), false);
#pragma unroll
    for (int m = 0; m < 8; m++) {
        sB[go + sw(lane + 64 * m)] = cmul(v[m], w);
        w = cmul(w, ws);
    }
    __syncthreads();
    for (int i = tid; i < 2048; i += 256) {
        const int c = i & 3, k2 = i >> 2;
        out[(size_t)k2 * 512 + colbase + c] = sB[c * 512 + sw(k2)];
    }
}

// h-prep pass1 (M2): direct-to-register load (t<32), reg FFT.
__device__ void dev_p1h(const float* __restrict__ h, float2* __restrict__ out,
                        int bx, int ch, float2* sA, float2* sB, float2* tw, int tid) {
    out += (size_t)ch * M2;
    const int colbase = bx * 4;
    const int g = tid >> 6, lane = tid & 63, go = g * 512;
    const int col = colbase + g;    // < 256
    load_tw(tw, tid);
    __syncthreads();
    float2 v[8];
#pragma unroll
    for (int m = 0; m < 8; m++) v[m] = make_float2(0.f, 0.f);
    if (lane < 32) {
        const int n = col + 256 * lane;
        const float hv = h[(size_t)ch * LH + n];
        const float2 cc = g_CX[n];
        v[0] = make_float2(hv * cc.x, hv * cc.y);
    }
    rfft512<false>(v, sA, sB, tw, go, lane);
    float2 w = wM<M2>((unsigned)(col * lane), false);
    const float2 ws = wM<M2>((unsigned)(64 * col), false);
#pragma unroll
    for (int m = 0; m < 8; m++) {
        sA[go + sw(lane + 64 * m)] = cmul(v[m], w);
        w = cmul(w, ws);
    }
    __syncthreads();
    for (int i = tid; i < 2048; i += 256) {
        const int c = i & 3, k2 = i >> 2;
        out[(size_t)k2 * 256 + colbase + c] = sA[c * 512 + sw(k2)];
    }
}

// B1h chirp generator pass1 (M2) — old style (precompute-only)
__device__ void dev_p1b(float2* __restrict__ out, int bx,
                        float2* sA, float2* sB, float2* tw, int tid) {
    const int colbase = bx * 4;
    load_tw(tw, tid);
    for (int i = tid; i < 4 * 512; i += 256) {
        const int c = i & 3, t = i >> 2;
        const int n = (colbase + c) + 256 * t;
        float2 v = make_float2(0.f, 0.f);
        if (n < KK)                 v = chirp(n, NN1, 1.f);
        else if (n >= M2 - LH + 1)  v = chirp((long long)(M2 - n), NN1, 1.f);
        sA[sw(c * 512 + t)] = v;
    }
    __syncthreads();
    float2* res = block_fft8<512, 4, false>(sA, sB, tw, tid);
    for (int i = tid; i < 4 * 512; i += 256) {
        const int c = i & 3, k2 = i >> 2;
        const int col = colbase + c;
        out[(size_t)k2 * 256 + col] =
            cmul(res[sw(c * 512 + k2)], wM<M2>((unsigned)(col * k2), false));
    }
}

// filter generator pass1 (M1) — old style
__device__ void dev_p1f(float2* __restrict__ out, int bx, int which,
                        float2* sA, float2* sB, float2* tw, int tid) {
    out += (size_t)which * M1;
    const int colbase = bx * 4;
    load_tw(tw, tid);
    for (int i = tid; i < 4 * 512; i += 256) {
        const int c = i & 3, t = i >> 2;
        const int n = (colbase + c) + 512 * t;
        float2 v = make_float2(0.f, 0.f);
        if (which == 0) {
            if (n < KK)                 v = chirp(n, NN1, 1.f);
            else if (n >= M1 - LX + 1)  v = chirp((long long)(M1 - n), NN1, 1.f);
        } else {
            if (n < LX)                 v = chirp(n, NN2, -1.f);
            else if (n >= M1 - KK + 1)  v = chirp((long long)(M1 - n), NN2, -1.f);
        }
        sA[sw(c * 512 + t)] = v;
    }
    __syncthreads();
    float2* res = block_fft8<512, 4, false>(sA, sB, tw, tid);
    for (int i = tid; i < 4 * 512; i += 256) {
        const int c = i & 3, k2 = i >> 2;
        const int col = colbase + c;
        out[(size_t)k2 * 512 + col] =
            cmul(res[sw(c * 512 + k2)], wM<M1>((unsigned)(col * k2), false));
    }
}

// pass2 writing TRANSPOSED filter layout out[kLow*NHI + kHigh]
template <int MSZ, int NA>
__device__ void dev_p2t(const float2* __restrict__ in, float2* __restrict__ out,
                        int bx, float2* sA, float2* sB, float2* tw, int tid) {
    const int rowbase = bx * 4;
    load_tw(tw, tid);
    for (int i = tid; i < 4 * NA; i += 256) {
        const int c = i / NA, n1 = i % NA;
        sA[sw(c * NA + n1)] = in[(size_t)(rowbase + c) * NA + n1];
    }
    __syncthreads();
    float2* res = block_fft8<NA, 4, false>(sA, sB, tw, tid);
    constexpr int NHI = NA;   // k1 range == FFT length
    for (int i = tid; i < 4 * NA; i += 256) {
        const int c = i & 3, k1 = i >> 2;
        out[(size_t)(rowbase + c) * NHI + k1] = res[sw(c * NA + k1)];
    }
}

// fused M1: regFFT(fwd, global in) -> *filtT (regs) -> regFFT(inv) -> out
__device__ void dev_fusedM1(const float2* __restrict__ in, const float2* __restrict__ filtT,
                            float2* __restrict__ out, int bx, int ch,
                            float2* sA, float2* sB, float2* tw, int tid) {
    in  += (size_t)ch * M1;
    out += (size_t)ch * M1;
    const int rowbase = bx * 4;
    const int g = tid >> 6, lane = tid & 63, go = g * 512;
    const int col = rowbase + g;
    load_tw(tw, tid);
    __syncthreads();
    const float2* gp = in + (size_t)col * 512;
    float2 v[8];
#pragma unroll
    for (int m = 0; m < 8; m++) v[m] = gp[lane + 64 * m];
    rfft512<false>(v, sA, sB, tw, go, lane);
    const float2* fp = filtT + (size_t)col * 512;
#pragma unroll
    for (int m = 0; m < 8; m++) v[m] = cmul(v[m], fp[lane + 64 * m]);
    rfft512<true>(v, sA, sB, tw, go, lane);
    float2 w = wM<M1>((unsigned)(col * lane), true);
    const float2 ws = wM<M1>((unsigned)(64 * col), true);
#pragma unroll
    for (int m = 0; m < 8; m++) {
        sA[go + sw(lane + 64 * m)] = cmul(v[m], w);
        w = cmul(w, ws);
    }
    __syncthreads();
    for (int i = tid; i < 2048; i += 256) {
        const int c = i & 3, k2p = i >> 2;
        out[(size_t)k2p * 512 + rowbase + c] = sA[c * 512 + sw(k2p)];
    }
}

// fused combine: FFT256(inv h rows) -> sH; regFFT(inv) -> *sH*PCT (regs) -> regFFT(fwd)
__device__ void dev_fusedComb(const float2* __restrict__ in, const float2* __restrict__ hs2,
                              float2* __restrict__ out, int bx, int ch,
                              float2* sA, float2* sB, float2* tw, float2* sH, int tid) {
    in  += (size_t)ch * M1;
    out += (size_t)ch * M1;
    hs2 += (size_t)ch * M2;
    const int rowbase = bx * 4;
    const int g = tid >> 6, lane = tid & 63, go = g * 512;
    const int col = rowbase + g;
    load_tw(tw, tid);
    __syncthreads();
    {   // step A: 4 x inverse FFT256 of hs2 rows (old style)
        const int goH = g * 256;
        const float2* hp = hs2 + (size_t)col * 256;
        st8_f<true, 256, 64>([&](int idx) { return hp[idx]; }, sB, tw, goH, lane);
        fft256_rest<true, 64>(sB, sA, tw, goH, lane);      // result in sB
        for (int i = tid; i < 4 * 136; i += 256) {
            const int c = i / 136, k1 = i % 136;
            sH[c * 136 + k1] = sB[c * 256 + sw(k1)];
        }
        __syncthreads();
    }
    const float2* gp = in + (size_t)col * 512;
    float2 v[8];
#pragma unroll
    for (int m = 0; m < 8; m++) v[m] = gp[lane + 64 * m];
    rfft512<true>(v, sA, sB, tw, go, lane);
    {   // combine in regs: idx = lane+64m < 136 else 0
        const float2* pp = g_PCT + (size_t)col * 136;
        v[0] = cmul(cmul(v[0], sH[g * 136 + lane]), pp[lane]);
        v[1] = cmul(cmul(v[1], sH[g * 136 + lane + 64]), pp[lane + 64]);
        v[2] = (lane < 8) ? cmul(cmul(v[2], sH[g * 136 + lane + 128]), pp[lane + 128])
                          : make_float2(0.f, 0.f);
#pragma unroll
        for (int m = 3; m < 8; m++) v[m] = make_float2(0.f, 0.f);
    }
    rfft512<false>(v, sA, sB, tw, go, lane);
    float2 w = wM<M1>((unsigned)(col * lane), false);
    const float2 ws = wM<M1>((unsigned)(64 * col), false);
#pragma unroll
    for (int m = 0; m < 8; m++) {
        sA[go + sw(lane + 64 * m)] = cmul(v[m], w);
        w = cmul(w, ws);
    }
    __syncthreads();
    for (int i = tid; i < 2048; i += 256) {
        const int c = i & 3, k2p = i >> 2;
        out[(size_t)k2p * 512 + rowbase + c] = sA[c * 512 + sw(k2p)];
    }
}

// fused M2: FFT256(fwd, old style) -> reorg+*B1fhT into regs -> regFFT(inv)
__device__ void dev_fusedM2(const float2* __restrict__ in, const float2* __restrict__ filtT,
                            float2* __restrict__ out, int bx, int ch,
                            float2* sA, float2* sB, float2* tw, int tid) {
    in  += (size_t)ch * M2;
    out += (size_t)ch * M2;
    const int r = bx * 4;
    load_tw(tw, tid);
    __syncthreads();
    {   // first FFT: 8 transforms of 256
        const int g8 = tid >> 5, lane8 = tid & 31, go8 = g8 * 256;
        const int row = r + (g8 & 3) + 256 * (g8 >> 2);
        const float2* gp = in + (size_t)row * 256;
        st8_f<false, 256, 32>([&](int idx) { return gp[idx]; }, sB, tw, go8, lane8);
        fft256_rest<false, 32>(sB, sA, tw, go8, lane8);    // result in sB
    }
    const int c0 = tid >> 6, lane = tid & 63, go = c0 * 512;
    float2 v[8];
#pragma unroll
    for (int m = 0; m < 8; m++) {
        const int idx = lane + 64 * m;
        const int k1 = idx >> 1, hi = idx & 1;
        v[m] = cmul(sB[(c0 + 4 * hi) * 256 + sw(k1)],
                    filtT[(size_t)(r + c0 + 256 * hi) * 256 + k1]);
    }
    rfft512<true>(v, sA, sB, tw, go, lane);
    const int col = r + c0;
    float2 w = wM<M2>((unsigned)(col * lane), true);
    const float2 ws = wM<M2>((unsigned)(64 * col), true);
#pragma unroll
    for (int m = 0; m < 8; m++) {
        sA[go + sw(lane + 64 * m)] = cmul(v[m], w);
        w = cmul(w, ws);
    }
    __syncthreads();
    for (int i = tid; i < 2048; i += 256) {
        const int c = i & 3, k2p = i >> 2;
        out[(size_t)k2p * 256 + r + c] = sA[c * 512 + sw(k2p)];
    }
}

// final: regFFT(inv) -> chirp(CFT) -> real output (staged for 16B sectors)
__device__ void dev_p2f(const float2* __restrict__ in, float* __restrict__ y,
                        int bx, int ch, float2* sA, float2* sB, float2* tw, int tid) {
    in += (size_t)ch * M1;
    const int rowbase = bx * 4;
    const int g = tid >> 6, lane = tid & 63, go = g * 512;
    const int col = rowbase + g;
    load_tw(tw, tid);
    __syncthreads();
    const float2* gp = in + (size_t)col * 512;
    float2 v[8];
#pragma unroll
    for (int m = 0; m < 8; m++) v[m] = gp[lane + 64 * m];
    rfft512<true>(v, sA, sB, tw, go, lane);
    float* sf = reinterpret_cast<float*>(sA);
    const float2* cp = g_CFT + (size_t)col * 256;
#pragma unroll
    for (int m = 0; m < 4; m++) {               // idx >= 256 -> outside y
        const int idx = lane + 64 * m;
        const float2 cf = cp[idx];
        sf[g * 256 + sw(idx)] = v[m].x * cf.x - v[m].y * cf.y;
    }
    __syncthreads();
    for (int i = tid; i < 1024; i += 256) {
        const int c = i & 3, k1 = i >> 2;
        y[(size_t)ch * LX + (rowbase + c) + 512 * k1] = sf[c * 256 + sw(k1)];
    }
}

// ================= merged __global__ kernels ==================================

__global__ void __launch_bounds__(256) k_init() {
    const int tid = threadIdx.x;
    if (blockIdx.x == 0) {
        for (int j = tid; j < 512; j += 256) {
            const double a = -2.0 * PI_D * (double)j;
            double s, c;
            sincos(a / 512.0, &s, &c);       g_T512[j] = make_float2((float)c, (float)s);
            sincos(a / (double)M1, &s, &c);  g_TM1[j]  = make_float2((float)c, (float)s);
            sincos(a / (double)M2, &s, &c);  g_TM2[j]  = make_float2((float)c, (float)s);
        }
        return;
    }
    const int i = (blockIdx.x - 1) * 256 + tid;   // < LX
    g_CX[i] = chirp(i, NN1, -1.f);
    {
        const float2 cf = chirp(i, NN2, 1.f);
        constexpr float INVM1 = 1.0f / (float)M1;
        g_CFT[(size_t)(i & 511) * 256 + (i >> 9)] =
            make_float2(cf.x * INVM1, cf.y * INVM1);
    }
    if (i < KK) {
        const long long kk = (long long)i * i;
        const long long ra = (2LL * kk) % (2LL * NN1);
        const long long rb = kk % (2LL * NN2);
        const double ang = -(double)ra * (PI_D / (double)NN1)
                           + (double)rb * (PI_D / (double)NN2);
        float sn, cs;
        sincosf((float)ang, &sn, &cs);
        constexpr float SC0 = (float)(2.0 / ((double)NN2 * (double)M1 * (double)M2));
        const float sc = (i == 0 || i == KK - 1) ? 0.5f * SC0 : SC0;
        g_PCT[(size_t)(i & 511) * 136 + (i >> 9)] = make_float2(cs * sc, sn * sc);
    }
}

__global__ void __launch_bounds__(256) k_m1(const float* __restrict__ h,
                                            float2* __restrict__ bufA,
                                            float2* __restrict__ hs1) {
    __shared__ float2 sA[2048], sB[2048], tw[512];
    const int tid = threadIdx.x;
    const int bx = blockIdx.x;
    if (bx < 128)       dev_p1f(bufA, bx, 0, sA, sB, tw, tid);
    else if (bx < 256)  dev_p1f(bufA, bx - 128, 1, sA, sB, tw, tid);
    else if (bx < 320)  dev_p1b(bufA + 2 * (size_t)M1, bx - 256, sA, sB, tw, tid);
    else {
        const int vb = bx - 320;
        dev_p1h(h, hs1, vb & 63, vb >> 6, sA, sB, tw, tid);
    }
}

__global__ void __launch_bounds__(256) k_m2(const float* __restrict__ x,
                                            const float2* __restrict__ bufA,
                                            float2* __restrict__ FM1T,
                                            float2* __restrict__ B1fhT,
                                            float2* __restrict__ bufB) {
    __shared__ float2 sA[2048], sB[2048], tw[512];
    const int tid = threadIdx.x;
    const int bx = blockIdx.x;
    if (bx < 128)       dev_p2t<M1, 512>(bufA, FM1T, bx, sA, sB, tw, tid);
    else if (bx < 256)  dev_p2t<M1, 512>(bufA + M1, FM1T + M1, bx - 128, sA, sB, tw, tid);
    else if (bx < 384)  dev_p2t<M2, 256>(bufA + 2 * (size_t)M1, B1fhT, bx - 256, sA, sB, tw, tid);
    else {
        const int vb = bx - 384;
        dev_p1x(x, bufB, vb & 127, vb >> 7, sA, sB, tw, tid);
    }
}

__global__ void __launch_bounds__(256) k_m3(const float2* __restrict__ bufB,
                                            const float2* __restrict__ FM1T,
                                            float2* __restrict__ bufA,
                                            const float2* __restrict__ hs1,
                                            const float2* __restrict__ B1fhT,
                                            float2* __restrict__ hs2) {
    __shared__ float2 sA[2048], sB[2048], tw[512];
    const int tid = threadIdx.x;
    const int bx = blockIdx.x;
    if (bx < 8192) {
        dev_fusedM1(bufB, FM1T, bufA, bx & 127, bx >> 7, sA, sB, tw, tid);
    } else {
        const int vb = bx - 8192;
        dev_fusedM2(hs1, B1fhT, hs2, vb & 63, vb >> 6, sA, sB, tw, tid);
    }
}

__global__ void __launch_bounds__(256) k_comb(const float2* __restrict__ in,
                                              const float2* __restrict__ hs2,
                                              float2* __restrict__ out) {
    __shared__ float2 sA[2048], sB[2048], tw[512], sH[4 * 136];
    dev_fusedComb(in, hs2, out, blockIdx.x, blockIdx.y, sA, sB, tw, sH, threadIdx.x);
}

__global__ void __launch_bounds__(256) k_f2(const float2* __restrict__ in,
                                            const float2* __restrict__ filtT,
                                            float2* __restrict__ out) {
    __shared__ float2 sA[2048], sB[2048], tw[512];
    dev_fusedM1(in, filtT, out, blockIdx.x, blockIdx.y, sA, sB, tw, threadIdx.x);
}

__global__ void __launch_bounds__(256) k_p2f(const float2* __restrict__ in,
                                             float* __restrict__ y) {
    __shared__ float2 sA[2048], sB[2048], tw[512];
    dev_p2f(in, y, blockIdx.x, blockIdx.y, sA, sB, tw, threadIdx.x);
}

// ---------------- launcher ---------------------------------------------------
extern "C" void kernel_launch(void* const* d_in, const int* in_sizes, int n_in,
                              void* d_out, int out_size) {
    const float* x = (const float*)d_in[0];
    const float* h = (const float*)d_in[1];
    float* y = (float*)d_out;

    float2 *bufA, *bufB, *bufC, *FM1T, *B1fhT;
    cudaGetSymbolAddress((void**)&bufA, g_bufA);
    cudaGetSymbolAddress((void**)&bufB, g_bufB);
    cudaGetSymbolAddress((void**)&bufC, g_bufC);
    cudaGetSymbolAddress((void**)&FM1T,  g_FM1);
    cudaGetSymbolAddress((void**)&B1fhT, g_B1fh);
    float2* hs1 = bufC;
    float2* hs2 = bufC + (size_t)NCH * M2;

    k_init<<<513, 256>>>();
    k_m1<<<320 + 64 * NCH, 256>>>(h, bufA, hs1);
    k_m2<<<384 + 128 * NCH, 256>>>(x, bufA, FM1T, B1fhT, bufB);
    k_m3<<<128 * NCH + 64 * NCH, 256>>>(bufB, FM1T, bufA, hs1, B1fhT, hs2);
    k_comb<<<dim3(128, NCH), 256>>>(bufA, hs2, bufB);
    k_f2<<<dim3(128, NCH), 256>>>(bufB, FM1T + M1, bufA);
    k_p2f<<<dim3(128, NCH), 256>>>(bufA, y);
}